// round 10
// baseline (speedup 1.0000x reference)
#include <cuda_runtime.h>
#include <math.h>
#include <stdint.h>

// Problem constants
constexpr int BATCH = 4;
constexpr int SEQ   = 2048;
constexpr int DIM   = 768;
constexpr int HEADS = 12;
constexpr int DH    = 64;              // head dim
constexpr int MROWS = BATCH * SEQ;     // 8192
constexpr float SCALE = 0.03608439182435161f;  // 768^-0.5

// ---------------------------------------------------------------------------
// Scratch (allocation-free: __device__ globals)
// ---------------------------------------------------------------------------
__device__ __align__(16) float g_q[(size_t)BATCH * HEADS * SEQ * DH];
__device__ __align__(16) float g_k[(size_t)BATCH * HEADS * SEQ * DH];
__device__ __align__(16) float g_v[(size_t)BATCH * HEADS * SEQ * DH];
__device__ __align__(16) float g_att[(size_t)BATCH * SEQ * DIM];

// ---------------------------------------------------------------------------
// Conversion helpers
// ---------------------------------------------------------------------------
__device__ __forceinline__ uint32_t cvt_tf32(float f) {
    uint32_t r;
    asm("cvt.rna.tf32.f32 %0, %1;" : "=r"(r) : "f"(f));
    return r;
}

// pack two floats to bf16x2 word: f0 -> low half, f1 -> high half
__device__ __forceinline__ uint32_t cvt2_bf16(float f0, float f1) {
    uint32_t r;
    asm("cvt.rn.bf16x2.f32 %0, %2, %1;" : "=r"(r) : "f"(f0), "f"(f1));
    return r;
}
__device__ __forceinline__ float bf16lo_f(uint32_t w) { return __uint_as_float(w << 16); }
__device__ __forceinline__ float bf16hi_f(uint32_t w) { return __uint_as_float(w & 0xffff0000u); }

// tf32 m16n8k8 mma (attention)
__device__ __forceinline__ void mma8(float& c0, float& c1, float& c2, float& c3,
                                     uint32_t a0, uint32_t a1, uint32_t a2, uint32_t a3,
                                     uint32_t b0, uint32_t b1) {
    asm volatile(
        "mma.sync.aligned.m16n8k8.row.col.f32.tf32.tf32.f32 "
        "{%0,%1,%2,%3}, {%4,%5,%6,%7}, {%8,%9}, {%0,%1,%2,%3};\n"
        : "+f"(c0), "+f"(c1), "+f"(c2), "+f"(c3)
        : "r"(a0), "r"(a1), "r"(a2), "r"(a3), "r"(b0), "r"(b1));
}

// bf16 m16n8k16 mma (projections)
__device__ __forceinline__ void mma16(float& c0, float& c1, float& c2, float& c3,
                                      uint32_t a0, uint32_t a1, uint32_t a2, uint32_t a3,
                                      uint32_t b0, uint32_t b1) {
    asm volatile(
        "mma.sync.aligned.m16n8k16.row.col.f32.bf16.bf16.f32 "
        "{%0,%1,%2,%3}, {%4,%5,%6,%7}, {%8,%9}, {%0,%1,%2,%3};\n"
        : "+f"(c0), "+f"(c1), "+f"(c2), "+f"(c3)
        : "r"(a0), "r"(a1), "r"(a2), "r"(a3), "r"(b0), "r"(b1));
}

// scatter one QKV element into g_q/g_k/g_v ([b,h,n,d] layout)
__device__ __forceinline__ void scatter_qkv(float v, int row, int col) {
    const int bb = row >> 11, nn = row & 2047;
    const int which = col / DIM;
    const int rem = col - which * DIM;
    const int head = rem >> 6, dd = rem & 63;
    float* dst = (which == 0) ? g_q : (which == 1) ? g_k : g_v;
    dst[((size_t)((bb * HEADS + head) * SEQ + nn) << 6) + dd] = v;
}

// ---------------------------------------------------------------------------
// Split-bf16 (3-term) GEMM bodies. Block 128x64, BK=16, 256 threads,
// 8 warps as 4M x 2N, warp tile 32x32. acc = 8 float4/thread.
// NON-TEMPLATED: two standalone kernels (qkv scatter / plain store).
// smem words are bf16x2 k-pairs; 8 words per 16-k row, stride 9.
// ---------------------------------------------------------------------------
constexpr int WST = 9;

__global__ __launch_bounds__(256)
void gemm_qkv_bf16(const float* __restrict__ A, const float* __restrict__ W,
                   const float* __restrict__ bias)
{
    __shared__ uint32_t AhS[128 * WST], AlS[128 * WST];
    __shared__ uint32_t BhS[64 * WST],  BlS[64 * WST];

    const int tid = threadIdx.x;
    const int lane = tid & 31;
    const int gid = lane >> 2, tig = lane & 3;
    const int w = tid >> 5;
    const int wm = w >> 1;
    const int wn = w & 1;
    const int rowBase = blockIdx.y * 128;
    const int colBase = blockIdx.x * 64;

    const int l_row  = tid >> 1;
    const int l_kf   = (tid & 1) * 8;
    const int l_rowB = tid >> 2;
    const int l_kfB  = (tid & 3) * 4;

    float4 acc[8];
    #pragma unroll
    for (int t = 0; t < 8; t++) acc[t] = make_float4(0.f, 0.f, 0.f, 0.f);

    const float* Aptr = A + (size_t)(rowBase + l_row) * DIM + l_kf;
    const float* Bptr = W + (size_t)(colBase + l_rowB) * DIM + l_kfB;

    float4 pa0 = *(const float4*)(Aptr);
    float4 pa1 = *(const float4*)(Aptr + 4);
    float4 pb0 = *(const float4*)(Bptr);

    for (int k0 = 0; k0 < DIM; k0 += 16) {
        {
            const int base = l_row * WST + (l_kf >> 1);
            uint32_t h;
            h = cvt2_bf16(pa0.x, pa0.y); AhS[base + 0] = h;
            AlS[base + 0] = cvt2_bf16(pa0.x - bf16lo_f(h), pa0.y - bf16hi_f(h));
            h = cvt2_bf16(pa0.z, pa0.w); AhS[base + 1] = h;
            AlS[base + 1] = cvt2_bf16(pa0.z - bf16lo_f(h), pa0.w - bf16hi_f(h));
            h = cvt2_bf16(pa1.x, pa1.y); AhS[base + 2] = h;
            AlS[base + 2] = cvt2_bf16(pa1.x - bf16lo_f(h), pa1.y - bf16hi_f(h));
            h = cvt2_bf16(pa1.z, pa1.w); AhS[base + 3] = h;
            AlS[base + 3] = cvt2_bf16(pa1.z - bf16lo_f(h), pa1.w - bf16hi_f(h));
        }
        {
            const int base = l_rowB * WST + (l_kfB >> 1);
            uint32_t h;
            h = cvt2_bf16(pb0.x, pb0.y); BhS[base + 0] = h;
            BlS[base + 0] = cvt2_bf16(pb0.x - bf16lo_f(h), pb0.y - bf16hi_f(h));
            h = cvt2_bf16(pb0.z, pb0.w); BhS[base + 1] = h;
            BlS[base + 1] = cvt2_bf16(pb0.z - bf16lo_f(h), pb0.w - bf16hi_f(h));
        }
        __syncthreads();
        if (k0 + 16 < DIM) {
            pa0 = *(const float4*)(Aptr + k0 + 16);
            pa1 = *(const float4*)(Aptr + k0 + 20);
            pb0 = *(const float4*)(Bptr + k0 + 16);
        }
        #pragma unroll
        for (int i = 0; i < 2; i++) {
            const int r0 = (wm * 32 + i * 16 + gid) * WST + tig;
            const int r1 = (wm * 32 + i * 16 + gid + 8) * WST + tig;
            const uint32_t ah0 = AhS[r0], ah1 = AhS[r1];
            const uint32_t ah2 = AhS[r0 + 4], ah3 = AhS[r1 + 4];
            const uint32_t al0 = AlS[r0], al1 = AlS[r1];
            const uint32_t al2 = AlS[r0 + 4], al3 = AlS[r1 + 4];
            #pragma unroll
            for (int j = 0; j < 4; j++) {
                const int cb = (wn * 32 + j * 8 + gid) * WST + tig;
                const uint32_t bh0 = BhS[cb], bh1 = BhS[cb + 4];
                const uint32_t bl0 = BlS[cb], bl1 = BlS[cb + 4];
                const int t = i * 4 + j;
                mma16(acc[t].x, acc[t].y, acc[t].z, acc[t].w,
                      ah0, ah1, ah2, ah3, bh0, bh1);
                mma16(acc[t].x, acc[t].y, acc[t].z, acc[t].w,
                      ah0, ah1, ah2, ah3, bl0, bl1);
                mma16(acc[t].x, acc[t].y, acc[t].z, acc[t].w,
                      al0, al1, al2, al3, bh0, bh1);
            }
        }
        __syncthreads();
    }

    #pragma unroll
    for (int i = 0; i < 2; i++) {
        const int r0 = rowBase + wm * 32 + i * 16 + gid;
        #pragma unroll
        for (int j = 0; j < 4; j++) {
            const int t = i * 4 + j;
            const int c0 = colBase + wn * 32 + j * 8 + tig * 2;
            const float b0v = bias[c0], b1v = bias[c0 + 1];
            scatter_qkv(acc[t].x + b0v, r0,     c0);
            scatter_qkv(acc[t].y + b1v, r0,     c0 + 1);
            scatter_qkv(acc[t].z + b0v, r0 + 8, c0);
            scatter_qkv(acc[t].w + b1v, r0 + 8, c0 + 1);
        }
    }
}

__global__ __launch_bounds__(256)
void gemm_out_bf16(const float* __restrict__ W, const float* __restrict__ bias,
                   float* __restrict__ out)
{
    __shared__ uint32_t AhS[128 * WST], AlS[128 * WST];
    __shared__ uint32_t BhS[64 * WST],  BlS[64 * WST];

    const int tid = threadIdx.x;
    const int lane = tid & 31;
    const int gid = lane >> 2, tig = lane & 3;
    const int w = tid >> 5;
    const int wm = w >> 1;
    const int wn = w & 1;
    const int rowBase = blockIdx.y * 128;
    const int colBase = blockIdx.x * 64;

    const int l_row  = tid >> 1;
    const int l_kf   = (tid & 1) * 8;
    const int l_rowB = tid >> 2;
    const int l_kfB  = (tid & 3) * 4;

    float4 acc[8];
    #pragma unroll
    for (int t = 0; t < 8; t++) acc[t] = make_float4(0.f, 0.f, 0.f, 0.f);

    const float* Aptr = g_att + (size_t)(rowBase + l_row) * DIM + l_kf;
    const float* Bptr = W + (size_t)(colBase + l_rowB) * DIM + l_kfB;

    float4 pa0 = *(const float4*)(Aptr);
    float4 pa1 = *(const float4*)(Aptr + 4);
    float4 pb0 = *(const float4*)(Bptr);

    for (int k0 = 0; k0 < DIM; k0 += 16) {
        {
            const int base = l_row * WST + (l_kf >> 1);
            uint32_t h;
            h = cvt2_bf16(pa0.x, pa0.y); AhS[base + 0] = h;
            AlS[base + 0] = cvt2_bf16(pa0.x - bf16lo_f(h), pa0.y - bf16hi_f(h));
            h = cvt2_bf16(pa0.z, pa0.w); AhS[base + 1] = h;
            AlS[base + 1] = cvt2_bf16(pa0.z - bf16lo_f(h), pa0.w - bf16hi_f(h));
            h = cvt2_bf16(pa1.x, pa1.y); AhS[base + 2] = h;
            AlS[base + 2] = cvt2_bf16(pa1.x - bf16lo_f(h), pa1.y - bf16hi_f(h));
            h = cvt2_bf16(pa1.z, pa1.w); AhS[base + 3] = h;
            AlS[base + 3] = cvt2_bf16(pa1.z - bf16lo_f(h), pa1.w - bf16hi_f(h));
        }
        {
            const int base = l_rowB * WST + (l_kfB >> 1);
            uint32_t h;
            h = cvt2_bf16(pb0.x, pb0.y); BhS[base + 0] = h;
            BlS[base + 0] = cvt2_bf16(pb0.x - bf16lo_f(h), pb0.y - bf16hi_f(h));
            h = cvt2_bf16(pb0.z, pb0.w); BhS[base + 1] = h;
            BlS[base + 1] = cvt2_bf16(pb0.z - bf16lo_f(h), pb0.w - bf16hi_f(h));
        }
        __syncthreads();
        if (k0 + 16 < DIM) {
            pa0 = *(const float4*)(Aptr + k0 + 16);
            pa1 = *(const float4*)(Aptr + k0 + 20);
            pb0 = *(const float4*)(Bptr + k0 + 16);
        }
        #pragma unroll
        for (int i = 0; i < 2; i++) {
            const int r0 = (wm * 32 + i * 16 + gid) * WST + tig;
            const int r1 = (wm * 32 + i * 16 + gid + 8) * WST + tig;
            const uint32_t ah0 = AhS[r0], ah1 = AhS[r1];
            const uint32_t ah2 = AhS[r0 + 4], ah3 = AhS[r1 + 4];
            const uint32_t al0 = AlS[r0], al1 = AlS[r1];
            const uint32_t al2 = AlS[r0 + 4], al3 = AlS[r1 + 4];
            #pragma unroll
            for (int j = 0; j < 4; j++) {
                const int cb = (wn * 32 + j * 8 + gid) * WST + tig;
                const uint32_t bh0 = BhS[cb], bh1 = BhS[cb + 4];
                const uint32_t bl0 = BlS[cb], bl1 = BlS[cb + 4];
                const int t = i * 4 + j;
                mma16(acc[t].x, acc[t].y, acc[t].z, acc[t].w,
                      ah0, ah1, ah2, ah3, bh0, bh1);
                mma16(acc[t].x, acc[t].y, acc[t].z, acc[t].w,
                      ah0, ah1, ah2, ah3, bl0, bl1);
                mma16(acc[t].x, acc[t].y, acc[t].z, acc[t].w,
                      al0, al1, al2, al3, bh0, bh1);
            }
        }
        __syncthreads();
    }

    #pragma unroll
    for (int i = 0; i < 2; i++) {
        const int r0 = rowBase + wm * 32 + i * 16 + gid;
        #pragma unroll
        for (int j = 0; j < 4; j++) {
            const int t = i * 4 + j;
            const int c0 = colBase + wn * 32 + j * 8 + tig * 2;
            const float b0v = bias[c0], b1v = bias[c0 + 1];
            out[(size_t)r0 * DIM + c0]           = acc[t].x + b0v;
            out[(size_t)r0 * DIM + c0 + 1]       = acc[t].y + b1v;
            out[(size_t)(r0 + 8) * DIM + c0]     = acc[t].z + b0v;
            out[(size_t)(r0 + 8) * DIM + c0 + 1] = acc[t].w + b1v;
        }
    }
}

// ---------------------------------------------------------------------------
// Flash attention, tf32 mma (UNCHANGED from passing R6 kernel).
// ---------------------------------------------------------------------------
constexpr int BC = 64;
constexpr int AST = 68;
constexpr int ATTN_SMEM = (128 + 64 + 64 + 128) * AST * 4;   // 104448 B

__global__ __launch_bounds__(256)
void attn_kernel()
{
    extern __shared__ uint32_t smu[];
    uint32_t* QS = smu;                 // [128][AST]
    uint32_t* KS = QS + 128 * AST;      // [64][AST]
    uint32_t* VS = KS + 64 * AST;       // [64][AST]
    uint32_t* PS = VS + 64 * AST;       // [128][AST]

    const int bh = blockIdx.x;
    const int qt = blockIdx.y;
    const int tid = threadIdx.x;
    const int lane = tid & 31;
    const int gid = lane >> 2, tig = lane & 3;
    const int w = tid >> 5;
    const int rb = w * 16;

    const float* Qg = g_q + (size_t)bh * SEQ * DH + (size_t)qt * 128 * DH;
    const float* Kg = g_k + (size_t)bh * SEQ * DH;
    const float* Vg = g_v + (size_t)bh * SEQ * DH;

    for (int idx = tid; idx < 128 * DH / 4; idx += 256) {
        const int row = idx >> 4, c4 = (idx & 15) * 4;
        float4 v = ((const float4*)Qg)[idx];
        QS[row * AST + c4 + 0] = cvt_tf32(v.x * SCALE);
        QS[row * AST + c4 + 1] = cvt_tf32(v.y * SCALE);
        QS[row * AST + c4 + 2] = cvt_tf32(v.z * SCALE);
        QS[row * AST + c4 + 3] = cvt_tf32(v.w * SCALE);
    }

    float4 o[8];
    #pragma unroll
    for (int j = 0; j < 8; j++) o[j] = make_float4(0.f, 0.f, 0.f, 0.f);
    float m0 = -3.0e38f, m1 = -3.0e38f;
    float l0 = 0.f, l1 = 0.f;

    for (int kt = 0; kt < SEQ / BC; kt++) {
        __syncthreads();
        const float4* Kg4 = (const float4*)(Kg + (size_t)kt * BC * DH);
        const float4* Vg4 = (const float4*)(Vg + (size_t)kt * BC * DH);
        for (int idx = tid; idx < BC * DH / 4; idx += 256) {
            const int key = idx >> 4, c4 = (idx & 15) * 4;
            float4 kv = Kg4[idx], vv = Vg4[idx];
            KS[key * AST + c4 + 0] = cvt_tf32(kv.x);
            KS[key * AST + c4 + 1] = cvt_tf32(kv.y);
            KS[key * AST + c4 + 2] = cvt_tf32(kv.z);
            KS[key * AST + c4 + 3] = cvt_tf32(kv.w);
            VS[key * AST + c4 + 0] = cvt_tf32(vv.x);
            VS[key * AST + c4 + 1] = cvt_tf32(vv.y);
            VS[key * AST + c4 + 2] = cvt_tf32(vv.z);
            VS[key * AST + c4 + 3] = cvt_tf32(vv.w);
        }
        __syncthreads();

        float4 s[8];
        #pragma unroll
        for (int j = 0; j < 8; j++) s[j] = make_float4(0.f, 0.f, 0.f, 0.f);
        #pragma unroll
        for (int kk = 0; kk < DH; kk += 8) {
            const int i0 = (rb + gid) * AST + kk + tig;
            const int i1 = (rb + gid + 8) * AST + kk + tig;
            const uint32_t a0 = QS[i0], a1 = QS[i1];
            const uint32_t a2 = QS[i0 + 4], a3 = QS[i1 + 4];
            #pragma unroll
            for (int j = 0; j < 8; j++) {
                const int bi = (j * 8 + gid) * AST + kk + tig;
                mma8(s[j].x, s[j].y, s[j].z, s[j].w,
                     a0, a1, a2, a3, KS[bi], KS[bi + 4]);
            }
        }

        float mt0 = -3.0e38f, mt1 = -3.0e38f;
        #pragma unroll
        for (int j = 0; j < 8; j++) {
            mt0 = fmaxf(mt0, fmaxf(s[j].x, s[j].y));
            mt1 = fmaxf(mt1, fmaxf(s[j].z, s[j].w));
        }
        mt0 = fmaxf(mt0, __shfl_xor_sync(0xffffffffu, mt0, 1));
        mt0 = fmaxf(mt0, __shfl_xor_sync(0xffffffffu, mt0, 2));
        mt1 = fmaxf(mt1, __shfl_xor_sync(0xffffffffu, mt1, 1));
        mt1 = fmaxf(mt1, __shfl_xor_sync(0xffffffffu, mt1, 2));
        const float mn0 = fmaxf(m0, mt0), mn1 = fmaxf(m1, mt1);
        const float al0 = __expf(m0 - mn0), al1 = __expf(m1 - mn1);
        m0 = mn0; m1 = mn1;

        float rs0 = 0.f, rs1 = 0.f;
        const int p0base = (rb + gid) * AST + tig * 2;
        const int p1base = (rb + gid + 8) * AST + tig * 2;
        #pragma unroll
        for (int j = 0; j < 8; j++) {
            const float e0 = __expf(s[j].x - mn0);
            const float e1 = __expf(s[j].y - mn0);
            const float e2 = __expf(s[j].z - mn1);
            const float e3 = __expf(s[j].w - mn1);
            rs0 += e0 + e1; rs1 += e2 + e3;
            PS[p0base + j * 8 + 0] = cvt_tf32(e0);
            PS[p0base + j * 8 + 1] = cvt_tf32(e1);
            PS[p1base + j * 8 + 0] = cvt_tf32(e2);
            PS[p1base + j * 8 + 1] = cvt_tf32(e3);
        }
        rs0 += __shfl_xor_sync(0xffffffffu, rs0, 1);
        rs0 += __shfl_xor_sync(0xffffffffu, rs0, 2);
        rs1 += __shfl_xor_sync(0xffffffffu, rs1, 1);
        rs1 += __shfl_xor_sync(0xffffffffu, rs1, 2);
        l0 = l0 * al0 + rs0;
        l1 = l1 * al1 + rs1;

        #pragma unroll
        for (int j = 0; j < 8; j++) {
            o[j].x *= al0; o[j].y *= al0;
            o[j].z *= al1; o[j].w *= al1;
        }
        __syncwarp();

        #pragma unroll
        for (int kk = 0; kk < BC; kk += 8) {
            const int i0 = (rb + gid) * AST + kk + tig;
            const int i1 = (rb + gid + 8) * AST + kk + tig;
            const uint32_t a0 = PS[i0], a1 = PS[i1];
            const uint32_t a2 = PS[i0 + 4], a3 = PS[i1 + 4];
            #pragma unroll
            for (int j = 0; j < 8; j++) {
                mma8(o[j].x, o[j].y, o[j].z, o[j].w,
                     a0, a1, a2, a3,
                     VS[(kk + tig) * AST + j * 8 + gid],
                     VS[(kk + tig + 4) * AST + j * 8 + gid]);
            }
        }
    }

    const int bb = bh / HEADS;
    const int head = bh % HEADS;
    const float inv0 = 1.0f / l0, inv1 = 1.0f / l1;
    const int n0 = qt * 128 + rb + gid;
    const int n1 = n0 + 8;
    float* dst0 = g_att + (size_t)(bb * SEQ + n0) * DIM + head * DH;
    float* dst1 = g_att + (size_t)(bb * SEQ + n1) * DIM + head * DH;
    #pragma unroll
    for (int j = 0; j < 8; j++) {
        const int col = j * 8 + tig * 2;
        dst0[col + 0] = o[j].x * inv0;
        dst0[col + 1] = o[j].y * inv0;
        dst1[col + 0] = o[j].z * inv1;
        dst1[col + 1] = o[j].w * inv1;
    }
}

// ---------------------------------------------------------------------------
// Launch
// ---------------------------------------------------------------------------
extern "C" void kernel_launch(void* const* d_in, const int* in_sizes, int n_in,
                              void* d_out, int out_size)
{
    const float* x     = (const float*)d_in[0];
    const float* w_qkv = (const float*)d_in[1];
    const float* b_qkv = (const float*)d_in[2];
    const float* w_out = (const float*)d_in[3];
    const float* b_out = (const float*)d_in[4];
    float* out = (float*)d_out;

    cudaFuncSetAttribute(attn_kernel,
                         cudaFuncAttributeMaxDynamicSharedMemorySize, ATTN_SMEM);

    // 1) QKV projection (split-bf16 tensor cores, scatter to [b,h,n,d])
    dim3 g1(3 * DIM / 64, MROWS / 128);   // (36, 64)
    gemm_qkv_bf16<<<g1, 256>>>(x, w_qkv, b_qkv);

    // 2) Flash attention (tf32 tensor cores)
    dim3 g2(BATCH * HEADS, SEQ / 128);    // (48, 16)
    attn_kernel<<<g2, 256, ATTN_SMEM>>>();

    // 3) Output projection (split-bf16 tensor cores; A = g_att internally)
    dim3 g3(DIM / 64, MROWS / 128);       // (12, 64)
    gemm_out_bf16<<<g3, 256>>>(w_out, b_out, out);
}

// round 11
// speedup vs baseline: 1.0021x; 1.0021x over previous
#include <cuda_runtime.h>
#include <math.h>
#include <stdint.h>

// Problem constants
constexpr int BATCH = 4;
constexpr int SEQ   = 2048;
constexpr int DIM   = 768;
constexpr int HEADS = 12;
constexpr int DH    = 64;              // head dim
constexpr int MROWS = BATCH * SEQ;     // 8192
constexpr float SCALE = 0.03608439182435161f;  // 768^-0.5

// ---------------------------------------------------------------------------
// Scratch (allocation-free: __device__ globals)
// ---------------------------------------------------------------------------
__device__ __align__(16) float g_q[(size_t)BATCH * HEADS * SEQ * DH];
__device__ __align__(16) float g_k[(size_t)BATCH * HEADS * SEQ * DH];
__device__ __align__(16) float g_v[(size_t)BATCH * HEADS * SEQ * DH];
__device__ __align__(16) float g_att[(size_t)BATCH * SEQ * DIM];

// ---------------------------------------------------------------------------
// Conversion helpers
// ---------------------------------------------------------------------------
__device__ __forceinline__ uint32_t cvt_tf32(float f) {
    uint32_t r;
    asm("cvt.rna.tf32.f32 %0, %1;" : "=r"(r) : "f"(f));
    return r;
}

// pack two floats to bf16x2 word: f0 -> low half, f1 -> high half
__device__ __forceinline__ uint32_t cvt2_bf16(float f0, float f1) {
    uint32_t r;
    asm("cvt.rn.bf16x2.f32 %0, %2, %1;" : "=r"(r) : "f"(f0), "f"(f1));
    return r;
}
__device__ __forceinline__ float bf16lo_f(uint32_t w) { return __uint_as_float(w << 16); }
__device__ __forceinline__ float bf16hi_f(uint32_t w) { return __uint_as_float(w & 0xffff0000u); }

// tf32 m16n8k8 mma (attention)
__device__ __forceinline__ void mma8(float& c0, float& c1, float& c2, float& c3,
                                     uint32_t a0, uint32_t a1, uint32_t a2, uint32_t a3,
                                     uint32_t b0, uint32_t b1) {
    asm volatile(
        "mma.sync.aligned.m16n8k8.row.col.f32.tf32.tf32.f32 "
        "{%0,%1,%2,%3}, {%4,%5,%6,%7}, {%8,%9}, {%0,%1,%2,%3};\n"
        : "+f"(c0), "+f"(c1), "+f"(c2), "+f"(c3)
        : "r"(a0), "r"(a1), "r"(a2), "r"(a3), "r"(b0), "r"(b1));
}

// bf16 m16n8k16 mma (projections)
__device__ __forceinline__ void mma16(float& c0, float& c1, float& c2, float& c3,
                                      uint32_t a0, uint32_t a1, uint32_t a2, uint32_t a3,
                                      uint32_t b0, uint32_t b1) {
    asm volatile(
        "mma.sync.aligned.m16n8k16.row.col.f32.bf16.bf16.f32 "
        "{%0,%1,%2,%3}, {%4,%5,%6,%7}, {%8,%9}, {%0,%1,%2,%3};\n"
        : "+f"(c0), "+f"(c1), "+f"(c2), "+f"(c3)
        : "r"(a0), "r"(a1), "r"(a2), "r"(a3), "r"(b0), "r"(b1));
}

// scatter one QKV element into g_q/g_k/g_v ([b,h,n,d] layout)
__device__ __forceinline__ void scatter_qkv(float v, int row, int col) {
    const int bb = row >> 11, nn = row & 2047;
    const int which = col / DIM;
    const int rem = col - which * DIM;
    const int head = rem >> 6, dd = rem & 63;
    float* dst = (which == 0) ? g_q : (which == 1) ? g_k : g_v;
    dst[((size_t)((bb * HEADS + head) * SEQ + nn) << 6) + dd] = v;
}

// ---------------------------------------------------------------------------
// Split-bf16 (3-term) GEMM bodies. Block 128x64, BK=16, 256 threads,
// 8 warps as 4M x 2N, warp tile 32x32. acc = 8 float4/thread.
// NON-TEMPLATED: two standalone kernels (qkv scatter / plain store).
// smem words are bf16x2 k-pairs; 8 words per 16-k row, stride 9.
// ---------------------------------------------------------------------------
constexpr int WST = 9;

__global__ __launch_bounds__(256)
void gemm_qkv_bf16(const float* __restrict__ A, const float* __restrict__ W,
                   const float* __restrict__ bias)
{
    __shared__ uint32_t AhS[128 * WST], AlS[128 * WST];
    __shared__ uint32_t BhS[64 * WST],  BlS[64 * WST];

    const int tid = threadIdx.x;
    const int lane = tid & 31;
    const int gid = lane >> 2, tig = lane & 3;
    const int w = tid >> 5;
    const int wm = w >> 1;
    const int wn = w & 1;
    const int rowBase = blockIdx.y * 128;
    const int colBase = blockIdx.x * 64;

    const int l_row  = tid >> 1;
    const int l_kf   = (tid & 1) * 8;
    const int l_rowB = tid >> 2;
    const int l_kfB  = (tid & 3) * 4;

    float4 acc[8];
    #pragma unroll
    for (int t = 0; t < 8; t++) acc[t] = make_float4(0.f, 0.f, 0.f, 0.f);

    const float* Aptr = A + (size_t)(rowBase + l_row) * DIM + l_kf;
    const float* Bptr = W + (size_t)(colBase + l_rowB) * DIM + l_kfB;

    float4 pa0 = *(const float4*)(Aptr);
    float4 pa1 = *(const float4*)(Aptr + 4);
    float4 pb0 = *(const float4*)(Bptr);

    for (int k0 = 0; k0 < DIM; k0 += 16) {
        {
            const int base = l_row * WST + (l_kf >> 1);
            uint32_t h;
            h = cvt2_bf16(pa0.x, pa0.y); AhS[base + 0] = h;
            AlS[base + 0] = cvt2_bf16(pa0.x - bf16lo_f(h), pa0.y - bf16hi_f(h));
            h = cvt2_bf16(pa0.z, pa0.w); AhS[base + 1] = h;
            AlS[base + 1] = cvt2_bf16(pa0.z - bf16lo_f(h), pa0.w - bf16hi_f(h));
            h = cvt2_bf16(pa1.x, pa1.y); AhS[base + 2] = h;
            AlS[base + 2] = cvt2_bf16(pa1.x - bf16lo_f(h), pa1.y - bf16hi_f(h));
            h = cvt2_bf16(pa1.z, pa1.w); AhS[base + 3] = h;
            AlS[base + 3] = cvt2_bf16(pa1.z - bf16lo_f(h), pa1.w - bf16hi_f(h));
        }
        {
            const int base = l_rowB * WST + (l_kfB >> 1);
            uint32_t h;
            h = cvt2_bf16(pb0.x, pb0.y); BhS[base + 0] = h;
            BlS[base + 0] = cvt2_bf16(pb0.x - bf16lo_f(h), pb0.y - bf16hi_f(h));
            h = cvt2_bf16(pb0.z, pb0.w); BhS[base + 1] = h;
            BlS[base + 1] = cvt2_bf16(pb0.z - bf16lo_f(h), pb0.w - bf16hi_f(h));
        }
        __syncthreads();
        if (k0 + 16 < DIM) {
            pa0 = *(const float4*)(Aptr + k0 + 16);
            pa1 = *(const float4*)(Aptr + k0 + 20);
            pb0 = *(const float4*)(Bptr + k0 + 16);
        }
        #pragma unroll
        for (int i = 0; i < 2; i++) {
            const int r0 = (wm * 32 + i * 16 + gid) * WST + tig;
            const int r1 = (wm * 32 + i * 16 + gid + 8) * WST + tig;
            const uint32_t ah0 = AhS[r0], ah1 = AhS[r1];
            const uint32_t ah2 = AhS[r0 + 4], ah3 = AhS[r1 + 4];
            const uint32_t al0 = AlS[r0], al1 = AlS[r1];
            const uint32_t al2 = AlS[r0 + 4], al3 = AlS[r1 + 4];
            #pragma unroll
            for (int j = 0; j < 4; j++) {
                const int cb = (wn * 32 + j * 8 + gid) * WST + tig;
                const uint32_t bh0 = BhS[cb], bh1 = BhS[cb + 4];
                const uint32_t bl0 = BlS[cb], bl1 = BlS[cb + 4];
                const int t = i * 4 + j;
                mma16(acc[t].x, acc[t].y, acc[t].z, acc[t].w,
                      ah0, ah1, ah2, ah3, bh0, bh1);
                mma16(acc[t].x, acc[t].y, acc[t].z, acc[t].w,
                      ah0, ah1, ah2, ah3, bl0, bl1);
                mma16(acc[t].x, acc[t].y, acc[t].z, acc[t].w,
                      al0, al1, al2, al3, bh0, bh1);
            }
        }
        __syncthreads();
    }

    #pragma unroll
    for (int i = 0; i < 2; i++) {
        const int r0 = rowBase + wm * 32 + i * 16 + gid;
        #pragma unroll
        for (int j = 0; j < 4; j++) {
            const int t = i * 4 + j;
            const int c0 = colBase + wn * 32 + j * 8 + tig * 2;
            const float b0v = bias[c0], b1v = bias[c0 + 1];
            scatter_qkv(acc[t].x + b0v, r0,     c0);
            scatter_qkv(acc[t].y + b1v, r0,     c0 + 1);
            scatter_qkv(acc[t].z + b0v, r0 + 8, c0);
            scatter_qkv(acc[t].w + b1v, r0 + 8, c0 + 1);
        }
    }
}

__global__ __launch_bounds__(256)
void gemm_out_bf16(const float* __restrict__ W, const float* __restrict__ bias,
                   float* __restrict__ out)
{
    __shared__ uint32_t AhS[128 * WST], AlS[128 * WST];
    __shared__ uint32_t BhS[64 * WST],  BlS[64 * WST];

    const int tid = threadIdx.x;
    const int lane = tid & 31;
    const int gid = lane >> 2, tig = lane & 3;
    const int w = tid >> 5;
    const int wm = w >> 1;
    const int wn = w & 1;
    const int rowBase = blockIdx.y * 128;
    const int colBase = blockIdx.x * 64;

    const int l_row  = tid >> 1;
    const int l_kf   = (tid & 1) * 8;
    const int l_rowB = tid >> 2;
    const int l_kfB  = (tid & 3) * 4;

    float4 acc[8];
    #pragma unroll
    for (int t = 0; t < 8; t++) acc[t] = make_float4(0.f, 0.f, 0.f, 0.f);

    const float* Aptr = g_att + (size_t)(rowBase + l_row) * DIM + l_kf;
    const float* Bptr = W + (size_t)(colBase + l_rowB) * DIM + l_kfB;

    float4 pa0 = *(const float4*)(Aptr);
    float4 pa1 = *(const float4*)(Aptr + 4);
    float4 pb0 = *(const float4*)(Bptr);

    for (int k0 = 0; k0 < DIM; k0 += 16) {
        {
            const int base = l_row * WST + (l_kf >> 1);
            uint32_t h;
            h = cvt2_bf16(pa0.x, pa0.y); AhS[base + 0] = h;
            AlS[base + 0] = cvt2_bf16(pa0.x - bf16lo_f(h), pa0.y - bf16hi_f(h));
            h = cvt2_bf16(pa0.z, pa0.w); AhS[base + 1] = h;
            AlS[base + 1] = cvt2_bf16(pa0.z - bf16lo_f(h), pa0.w - bf16hi_f(h));
            h = cvt2_bf16(pa1.x, pa1.y); AhS[base + 2] = h;
            AlS[base + 2] = cvt2_bf16(pa1.x - bf16lo_f(h), pa1.y - bf16hi_f(h));
            h = cvt2_bf16(pa1.z, pa1.w); AhS[base + 3] = h;
            AlS[base + 3] = cvt2_bf16(pa1.z - bf16lo_f(h), pa1.w - bf16hi_f(h));
        }
        {
            const int base = l_rowB * WST + (l_kfB >> 1);
            uint32_t h;
            h = cvt2_bf16(pb0.x, pb0.y); BhS[base + 0] = h;
            BlS[base + 0] = cvt2_bf16(pb0.x - bf16lo_f(h), pb0.y - bf16hi_f(h));
            h = cvt2_bf16(pb0.z, pb0.w); BhS[base + 1] = h;
            BlS[base + 1] = cvt2_bf16(pb0.z - bf16lo_f(h), pb0.w - bf16hi_f(h));
        }
        __syncthreads();
        if (k0 + 16 < DIM) {
            pa0 = *(const float4*)(Aptr + k0 + 16);
            pa1 = *(const float4*)(Aptr + k0 + 20);
            pb0 = *(const float4*)(Bptr + k0 + 16);
        }
        #pragma unroll
        for (int i = 0; i < 2; i++) {
            const int r0 = (wm * 32 + i * 16 + gid) * WST + tig;
            const int r1 = (wm * 32 + i * 16 + gid + 8) * WST + tig;
            const uint32_t ah0 = AhS[r0], ah1 = AhS[r1];
            const uint32_t ah2 = AhS[r0 + 4], ah3 = AhS[r1 + 4];
            const uint32_t al0 = AlS[r0], al1 = AlS[r1];
            const uint32_t al2 = AlS[r0 + 4], al3 = AlS[r1 + 4];
            #pragma unroll
            for (int j = 0; j < 4; j++) {
                const int cb = (wn * 32 + j * 8 + gid) * WST + tig;
                const uint32_t bh0 = BhS[cb], bh1 = BhS[cb + 4];
                const uint32_t bl0 = BlS[cb], bl1 = BlS[cb + 4];
                const int t = i * 4 + j;
                mma16(acc[t].x, acc[t].y, acc[t].z, acc[t].w,
                      ah0, ah1, ah2, ah3, bh0, bh1);
                mma16(acc[t].x, acc[t].y, acc[t].z, acc[t].w,
                      ah0, ah1, ah2, ah3, bl0, bl1);
                mma16(acc[t].x, acc[t].y, acc[t].z, acc[t].w,
                      al0, al1, al2, al3, bh0, bh1);
            }
        }
        __syncthreads();
    }

    #pragma unroll
    for (int i = 0; i < 2; i++) {
        const int r0 = rowBase + wm * 32 + i * 16 + gid;
        #pragma unroll
        for (int j = 0; j < 4; j++) {
            const int t = i * 4 + j;
            const int c0 = colBase + wn * 32 + j * 8 + tig * 2;
            const float b0v = bias[c0], b1v = bias[c0 + 1];
            out[(size_t)r0 * DIM + c0]           = acc[t].x + b0v;
            out[(size_t)r0 * DIM + c0 + 1]       = acc[t].y + b1v;
            out[(size_t)(r0 + 8) * DIM + c0]     = acc[t].z + b0v;
            out[(size_t)(r0 + 8) * DIM + c0 + 1] = acc[t].w + b1v;
        }
    }
}

// ---------------------------------------------------------------------------
// Flash attention, tf32 mma (UNCHANGED from passing R6 kernel).
// ---------------------------------------------------------------------------
constexpr int BC = 64;
constexpr int AST = 68;
constexpr int ATTN_SMEM = (128 + 64 + 64 + 128) * AST * 4;   // 104448 B

__global__ __launch_bounds__(256)
void attn_kernel()
{
    extern __shared__ uint32_t smu[];
    uint32_t* QS = smu;                 // [128][AST]
    uint32_t* KS = QS + 128 * AST;      // [64][AST]
    uint32_t* VS = KS + 64 * AST;       // [64][AST]
    uint32_t* PS = VS + 64 * AST;       // [128][AST]

    const int bh = blockIdx.x;
    const int qt = blockIdx.y;
    const int tid = threadIdx.x;
    const int lane = tid & 31;
    const int gid = lane >> 2, tig = lane & 3;
    const int w = tid >> 5;
    const int rb = w * 16;

    const float* Qg = g_q + (size_t)bh * SEQ * DH + (size_t)qt * 128 * DH;
    const float* Kg = g_k + (size_t)bh * SEQ * DH;
    const float* Vg = g_v + (size_t)bh * SEQ * DH;

    for (int idx = tid; idx < 128 * DH / 4; idx += 256) {
        const int row = idx >> 4, c4 = (idx & 15) * 4;
        float4 v = ((const float4*)Qg)[idx];
        QS[row * AST + c4 + 0] = cvt_tf32(v.x * SCALE);
        QS[row * AST + c4 + 1] = cvt_tf32(v.y * SCALE);
        QS[row * AST + c4 + 2] = cvt_tf32(v.z * SCALE);
        QS[row * AST + c4 + 3] = cvt_tf32(v.w * SCALE);
    }

    float4 o[8];
    #pragma unroll
    for (int j = 0; j < 8; j++) o[j] = make_float4(0.f, 0.f, 0.f, 0.f);
    float m0 = -3.0e38f, m1 = -3.0e38f;
    float l0 = 0.f, l1 = 0.f;

    for (int kt = 0; kt < SEQ / BC; kt++) {
        __syncthreads();
        const float4* Kg4 = (const float4*)(Kg + (size_t)kt * BC * DH);
        const float4* Vg4 = (const float4*)(Vg + (size_t)kt * BC * DH);
        for (int idx = tid; idx < BC * DH / 4; idx += 256) {
            const int key = idx >> 4, c4 = (idx & 15) * 4;
            float4 kv = Kg4[idx], vv = Vg4[idx];
            KS[key * AST + c4 + 0] = cvt_tf32(kv.x);
            KS[key * AST + c4 + 1] = cvt_tf32(kv.y);
            KS[key * AST + c4 + 2] = cvt_tf32(kv.z);
            KS[key * AST + c4 + 3] = cvt_tf32(kv.w);
            VS[key * AST + c4 + 0] = cvt_tf32(vv.x);
            VS[key * AST + c4 + 1] = cvt_tf32(vv.y);
            VS[key * AST + c4 + 2] = cvt_tf32(vv.z);
            VS[key * AST + c4 + 3] = cvt_tf32(vv.w);
        }
        __syncthreads();

        float4 s[8];
        #pragma unroll
        for (int j = 0; j < 8; j++) s[j] = make_float4(0.f, 0.f, 0.f, 0.f);
        #pragma unroll
        for (int kk = 0; kk < DH; kk += 8) {
            const int i0 = (rb + gid) * AST + kk + tig;
            const int i1 = (rb + gid + 8) * AST + kk + tig;
            const uint32_t a0 = QS[i0], a1 = QS[i1];
            const uint32_t a2 = QS[i0 + 4], a3 = QS[i1 + 4];
            #pragma unroll
            for (int j = 0; j < 8; j++) {
                const int bi = (j * 8 + gid) * AST + kk + tig;
                mma8(s[j].x, s[j].y, s[j].z, s[j].w,
                     a0, a1, a2, a3, KS[bi], KS[bi + 4]);
            }
        }

        float mt0 = -3.0e38f, mt1 = -3.0e38f;
        #pragma unroll
        for (int j = 0; j < 8; j++) {
            mt0 = fmaxf(mt0, fmaxf(s[j].x, s[j].y));
            mt1 = fmaxf(mt1, fmaxf(s[j].z, s[j].w));
        }
        mt0 = fmaxf(mt0, __shfl_xor_sync(0xffffffffu, mt0, 1));
        mt0 = fmaxf(mt0, __shfl_xor_sync(0xffffffffu, mt0, 2));
        mt1 = fmaxf(mt1, __shfl_xor_sync(0xffffffffu, mt1, 1));
        mt1 = fmaxf(mt1, __shfl_xor_sync(0xffffffffu, mt1, 2));
        const float mn0 = fmaxf(m0, mt0), mn1 = fmaxf(m1, mt1);
        const float al0 = __expf(m0 - mn0), al1 = __expf(m1 - mn1);
        m0 = mn0; m1 = mn1;

        float rs0 = 0.f, rs1 = 0.f;
        const int p0base = (rb + gid) * AST + tig * 2;
        const int p1base = (rb + gid + 8) * AST + tig * 2;
        #pragma unroll
        for (int j = 0; j < 8; j++) {
            const float e0 = __expf(s[j].x - mn0);
            const float e1 = __expf(s[j].y - mn0);
            const float e2 = __expf(s[j].z - mn1);
            const float e3 = __expf(s[j].w - mn1);
            rs0 += e0 + e1; rs1 += e2 + e3;
            PS[p0base + j * 8 + 0] = cvt_tf32(e0);
            PS[p0base + j * 8 + 1] = cvt_tf32(e1);
            PS[p1base + j * 8 + 0] = cvt_tf32(e2);
            PS[p1base + j * 8 + 1] = cvt_tf32(e3);
        }
        rs0 += __shfl_xor_sync(0xffffffffu, rs0, 1);
        rs0 += __shfl_xor_sync(0xffffffffu, rs0, 2);
        rs1 += __shfl_xor_sync(0xffffffffu, rs1, 1);
        rs1 += __shfl_xor_sync(0xffffffffu, rs1, 2);
        l0 = l0 * al0 + rs0;
        l1 = l1 * al1 + rs1;

        #pragma unroll
        for (int j = 0; j < 8; j++) {
            o[j].x *= al0; o[j].y *= al0;
            o[j].z *= al1; o[j].w *= al1;
        }
        __syncwarp();

        #pragma unroll
        for (int kk = 0; kk < BC; kk += 8) {
            const int i0 = (rb + gid) * AST + kk + tig;
            const int i1 = (rb + gid + 8) * AST + kk + tig;
            const uint32_t a0 = PS[i0], a1 = PS[i1];
            const uint32_t a2 = PS[i0 + 4], a3 = PS[i1 + 4];
            #pragma unroll
            for (int j = 0; j < 8; j++) {
                mma8(o[j].x, o[j].y, o[j].z, o[j].w,
                     a0, a1, a2, a3,
                     VS[(kk + tig) * AST + j * 8 + gid],
                     VS[(kk + tig + 4) * AST + j * 8 + gid]);
            }
        }
    }

    const int bb = bh / HEADS;
    const int head = bh % HEADS;
    const float inv0 = 1.0f / l0, inv1 = 1.0f / l1;
    const int n0 = qt * 128 + rb + gid;
    const int n1 = n0 + 8;
    float* dst0 = g_att + (size_t)(bb * SEQ + n0) * DIM + head * DH;
    float* dst1 = g_att + (size_t)(bb * SEQ + n1) * DIM + head * DH;
    #pragma unroll
    for (int j = 0; j < 8; j++) {
        const int col = j * 8 + tig * 2;
        dst0[col + 0] = o[j].x * inv0;
        dst0[col + 1] = o[j].y * inv0;
        dst1[col + 0] = o[j].z * inv1;
        dst1[col + 1] = o[j].w * inv1;
    }
}

// ---------------------------------------------------------------------------
// Launch
// ---------------------------------------------------------------------------
extern "C" void kernel_launch(void* const* d_in, const int* in_sizes, int n_in,
                              void* d_out, int out_size)
{
    const float* x     = (const float*)d_in[0];
    const float* w_qkv = (const float*)d_in[1];
    const float* b_qkv = (const float*)d_in[2];
    const float* w_out = (const float*)d_in[3];
    const float* b_out = (const float*)d_in[4];
    float* out = (float*)d_out;

    cudaFuncSetAttribute(attn_kernel,
                         cudaFuncAttributeMaxDynamicSharedMemorySize, ATTN_SMEM);

    // 1) QKV projection (split-bf16 tensor cores, scatter to [b,h,n,d])
    dim3 g1(3 * DIM / 64, MROWS / 128);   // (36, 64)
    gemm_qkv_bf16<<<g1, 256>>>(x, w_qkv, b_qkv);

    // 2) Flash attention (tf32 tensor cores)
    dim3 g2(BATCH * HEADS, SEQ / 128);    // (48, 16)
    attn_kernel<<<g2, 256, ATTN_SMEM>>>();

    // 3) Output projection (split-bf16 tensor cores; A = g_att internally)
    dim3 g3(DIM / 64, MROWS / 128);       // (12, 64)
    gemm_out_bf16<<<g3, 256>>>(w_out, b_out, out);
}

// round 13
// speedup vs baseline: 1.0980x; 1.0957x over previous
#include <cuda_runtime.h>
#include <math.h>
#include <stdint.h>

// Problem constants
constexpr int BATCH = 4;
constexpr int SEQ   = 2048;
constexpr int DIM   = 768;
constexpr int HEADS = 12;
constexpr int DH    = 64;              // head dim
constexpr int MROWS = BATCH * SEQ;     // 8192
constexpr float SCALE = 0.03608439182435161f;  // 768^-0.5

// ---------------------------------------------------------------------------
// Scratch (allocation-free: __device__ globals)
// ---------------------------------------------------------------------------
__device__ __align__(16) float g_q[(size_t)BATCH * HEADS * SEQ * DH];
__device__ __align__(16) float g_k[(size_t)BATCH * HEADS * SEQ * DH];
__device__ __align__(16) float g_v[(size_t)BATCH * HEADS * SEQ * DH];
__device__ __align__(16) float g_att[(size_t)BATCH * SEQ * DIM];

// ---------------------------------------------------------------------------
// Conversion helpers
// ---------------------------------------------------------------------------
__device__ __forceinline__ uint32_t cvt_tf32(float f) {
    uint32_t r;
    asm("cvt.rna.tf32.f32 %0, %1;" : "=r"(r) : "f"(f));
    return r;
}

// pack two floats to bf16x2 word: f0 -> low half, f1 -> high half
__device__ __forceinline__ uint32_t cvt2_bf16(float f0, float f1) {
    uint32_t r;
    asm("cvt.rn.bf16x2.f32 %0, %2, %1;" : "=r"(r) : "f"(f0), "f"(f1));
    return r;
}
__device__ __forceinline__ float bf16lo_f(uint32_t w) { return __uint_as_float(w << 16); }
__device__ __forceinline__ float bf16hi_f(uint32_t w) { return __uint_as_float(w & 0xffff0000u); }

// tf32 m16n8k8 mma (attention)
__device__ __forceinline__ void mma8(float& c0, float& c1, float& c2, float& c3,
                                     uint32_t a0, uint32_t a1, uint32_t a2, uint32_t a3,
                                     uint32_t b0, uint32_t b1) {
    asm volatile(
        "mma.sync.aligned.m16n8k8.row.col.f32.tf32.tf32.f32 "
        "{%0,%1,%2,%3}, {%4,%5,%6,%7}, {%8,%9}, {%0,%1,%2,%3};\n"
        : "+f"(c0), "+f"(c1), "+f"(c2), "+f"(c3)
        : "r"(a0), "r"(a1), "r"(a2), "r"(a3), "r"(b0), "r"(b1));
}

// bf16 m16n8k16 mma (projections)
__device__ __forceinline__ void mma16(float& c0, float& c1, float& c2, float& c3,
                                      uint32_t a0, uint32_t a1, uint32_t a2, uint32_t a3,
                                      uint32_t b0, uint32_t b1) {
    asm volatile(
        "mma.sync.aligned.m16n8k16.row.col.f32.bf16.bf16.f32 "
        "{%0,%1,%2,%3}, {%4,%5,%6,%7}, {%8,%9}, {%0,%1,%2,%3};\n"
        : "+f"(c0), "+f"(c1), "+f"(c2), "+f"(c3)
        : "r"(a0), "r"(a1), "r"(a2), "r"(a3), "r"(b0), "r"(b1));
}

// scatter one QKV element into g_q/g_k/g_v ([b,h,n,d] layout)
__device__ __forceinline__ void scatter_qkv(float v, int row, int col) {
    const int bb = row >> 11, nn = row & 2047;
    const int which = col / DIM;
    const int rem = col - which * DIM;
    const int head = rem >> 6, dd = rem & 63;
    float* dst = (which == 0) ? g_q : (which == 1) ? g_k : g_v;
    dst[((size_t)((bb * HEADS + head) * SEQ + nn) << 6) + dd] = v;
}

// ---------------------------------------------------------------------------
// Split-bf16 (3-term) GEMM. Block 128x64, BK=16, 256 threads, 8 warps as
// 4M x 2N, warp tile 32x32. smem: hi/lo INTERLEAVED per k-pair so fragment
// loads are single LDS.64; row stride 24 words (pair-stride 12 -> the pair
// index gid*12+tig is distinct mod 16 within each half-warp: conflict-free).
// Double-buffered tiles: ONE __syncthreads per k-step.
// NON-TEMPLATED twin kernels (templated duals trip the 128MiB mem guard).
// ---------------------------------------------------------------------------
constexpr int PST = 24;   // words per row: 8 kpairs * 2 (hi,lo) + 8 pad

__global__ __launch_bounds__(256)
void gemm_qkv_bf16(const float* __restrict__ A, const float* __restrict__ W,
                   const float* __restrict__ bias)
{
    __shared__ __align__(16) uint32_t AS[2][128 * PST];
    __shared__ __align__(16) uint32_t BS[2][64 * PST];

    const int tid = threadIdx.x;
    const int lane = tid & 31;
    const int gid = lane >> 2, tig = lane & 3;
    const int w = tid >> 5;
    const int wm = w >> 1;
    const int wn = w & 1;
    const int rowBase = blockIdx.y * 128;
    const int colBase = blockIdx.x * 64;

    const int l_row  = tid >> 1;          // A loader row 0..127
    const int l_kp   = (tid & 1) * 4;     // A loader kpair base 0 or 4
    const int l_rowB = tid >> 2;          // B loader row 0..63
    const int l_kpB  = (tid & 3) * 2;     // B loader kpair base 0,2,4,6

    float4 acc[8];
    #pragma unroll
    for (int t = 0; t < 8; t++) acc[t] = make_float4(0.f, 0.f, 0.f, 0.f);

    const float* Aptr = A + (size_t)(rowBase + l_row) * DIM + l_kp * 2;
    const float* Bptr = W + (size_t)(colBase + l_rowB) * DIM + l_kpB * 2;

    float4 pa0 = *(const float4*)(Aptr);
    float4 pa1 = *(const float4*)(Aptr + 4);
    float4 pb0 = *(const float4*)(Bptr);

    // store k-tile 0 into buffer 0
    {
        const int ab = l_row * PST + l_kp * 2;
        uint32_t h;
        h = cvt2_bf16(pa0.x, pa0.y);
        *(uint2*)&AS[0][ab + 0] = make_uint2(h, cvt2_bf16(pa0.x - bf16lo_f(h), pa0.y - bf16hi_f(h)));
        h = cvt2_bf16(pa0.z, pa0.w);
        *(uint2*)&AS[0][ab + 2] = make_uint2(h, cvt2_bf16(pa0.z - bf16lo_f(h), pa0.w - bf16hi_f(h)));
        h = cvt2_bf16(pa1.x, pa1.y);
        *(uint2*)&AS[0][ab + 4] = make_uint2(h, cvt2_bf16(pa1.x - bf16lo_f(h), pa1.y - bf16hi_f(h)));
        h = cvt2_bf16(pa1.z, pa1.w);
        *(uint2*)&AS[0][ab + 6] = make_uint2(h, cvt2_bf16(pa1.z - bf16lo_f(h), pa1.w - bf16hi_f(h)));
        const int bb2 = l_rowB * PST + l_kpB * 2;
        h = cvt2_bf16(pb0.x, pb0.y);
        *(uint2*)&BS[0][bb2 + 0] = make_uint2(h, cvt2_bf16(pb0.x - bf16lo_f(h), pb0.y - bf16hi_f(h)));
        h = cvt2_bf16(pb0.z, pb0.w);
        *(uint2*)&BS[0][bb2 + 2] = make_uint2(h, cvt2_bf16(pb0.z - bf16lo_f(h), pb0.w - bf16hi_f(h)));
    }

    int cur = 0;
    for (int k0 = 0; k0 < DIM; k0 += 16) {
        __syncthreads();                       // buffer 'cur' ready; prior reads of 'cur^1' done
        const bool more = (k0 + 16 < DIM);
        if (more) {
            pa0 = *(const float4*)(Aptr + k0 + 16);
            pa1 = *(const float4*)(Aptr + k0 + 20);
            pb0 = *(const float4*)(Bptr + k0 + 16);
        }
        #pragma unroll
        for (int i = 0; i < 2; i++) {
            const int r0 = (wm * 32 + i * 16 + gid) * PST + tig * 2;
            const int r1 = r0 + 8 * PST;
            const uint2 p00 = *(const uint2*)&AS[cur][r0];       // kpair tig
            const uint2 p01 = *(const uint2*)&AS[cur][r0 + 8];   // kpair tig+4
            const uint2 p10 = *(const uint2*)&AS[cur][r1];
            const uint2 p11 = *(const uint2*)&AS[cur][r1 + 8];
            #pragma unroll
            for (int j = 0; j < 4; j++) {
                const int cb = (wn * 32 + j * 8 + gid) * PST + tig * 2;
                const uint2 q0 = *(const uint2*)&BS[cur][cb];
                const uint2 q1 = *(const uint2*)&BS[cur][cb + 8];
                const int t = i * 4 + j;
                mma16(acc[t].x, acc[t].y, acc[t].z, acc[t].w,
                      p00.x, p10.x, p01.x, p11.x, q0.x, q1.x);   // hi*hi
                mma16(acc[t].x, acc[t].y, acc[t].z, acc[t].w,
                      p00.x, p10.x, p01.x, p11.x, q0.y, q1.y);   // hi*lo
                mma16(acc[t].x, acc[t].y, acc[t].z, acc[t].w,
                      p00.y, p10.y, p01.y, p11.y, q0.x, q1.x);   // lo*hi
            }
        }
        if (more) {
            const int nxt = cur ^ 1;
            const int ab = l_row * PST + l_kp * 2;
            uint32_t h;
            h = cvt2_bf16(pa0.x, pa0.y);
            *(uint2*)&AS[nxt][ab + 0] = make_uint2(h, cvt2_bf16(pa0.x - bf16lo_f(h), pa0.y - bf16hi_f(h)));
            h = cvt2_bf16(pa0.z, pa0.w);
            *(uint2*)&AS[nxt][ab + 2] = make_uint2(h, cvt2_bf16(pa0.z - bf16lo_f(h), pa0.w - bf16hi_f(h)));
            h = cvt2_bf16(pa1.x, pa1.y);
            *(uint2*)&AS[nxt][ab + 4] = make_uint2(h, cvt2_bf16(pa1.x - bf16lo_f(h), pa1.y - bf16hi_f(h)));
            h = cvt2_bf16(pa1.z, pa1.w);
            *(uint2*)&AS[nxt][ab + 6] = make_uint2(h, cvt2_bf16(pa1.z - bf16lo_f(h), pa1.w - bf16hi_f(h)));
            const int bb2 = l_rowB * PST + l_kpB * 2;
            h = cvt2_bf16(pb0.x, pb0.y);
            *(uint2*)&BS[nxt][bb2 + 0] = make_uint2(h, cvt2_bf16(pb0.x - bf16lo_f(h), pb0.y - bf16hi_f(h)));
            h = cvt2_bf16(pb0.z, pb0.w);
            *(uint2*)&BS[nxt][bb2 + 2] = make_uint2(h, cvt2_bf16(pb0.z - bf16lo_f(h), pb0.w - bf16hi_f(h)));
        }
        cur ^= 1;
    }

    #pragma unroll
    for (int i = 0; i < 2; i++) {
        const int r0 = rowBase + wm * 32 + i * 16 + gid;
        #pragma unroll
        for (int j = 0; j < 4; j++) {
            const int t = i * 4 + j;
            const int c0 = colBase + wn * 32 + j * 8 + tig * 2;
            const float b0v = bias[c0], b1v = bias[c0 + 1];
            scatter_qkv(acc[t].x + b0v, r0,     c0);
            scatter_qkv(acc[t].y + b1v, r0,     c0 + 1);
            scatter_qkv(acc[t].z + b0v, r0 + 8, c0);
            scatter_qkv(acc[t].w + b1v, r0 + 8, c0 + 1);
        }
    }
}

__global__ __launch_bounds__(256)
void gemm_out_bf16(const float* __restrict__ W, const float* __restrict__ bias,
                   float* __restrict__ out)
{
    __shared__ __align__(16) uint32_t AS[2][128 * PST];
    __shared__ __align__(16) uint32_t BS[2][64 * PST];

    const int tid = threadIdx.x;
    const int lane = tid & 31;
    const int gid = lane >> 2, tig = lane & 3;
    const int w = tid >> 5;
    const int wm = w >> 1;
    const int wn = w & 1;
    const int rowBase = blockIdx.y * 128;
    const int colBase = blockIdx.x * 64;

    const int l_row  = tid >> 1;
    const int l_kp   = (tid & 1) * 4;
    const int l_rowB = tid >> 2;
    const int l_kpB  = (tid & 3) * 2;

    float4 acc[8];
    #pragma unroll
    for (int t = 0; t < 8; t++) acc[t] = make_float4(0.f, 0.f, 0.f, 0.f);

    const float* Aptr = g_att + (size_t)(rowBase + l_row) * DIM + l_kp * 2;
    const float* Bptr = W + (size_t)(colBase + l_rowB) * DIM + l_kpB * 2;

    float4 pa0 = *(const float4*)(Aptr);
    float4 pa1 = *(const float4*)(Aptr + 4);
    float4 pb0 = *(const float4*)(Bptr);

    {
        const int ab = l_row * PST + l_kp * 2;
        uint32_t h;
        h = cvt2_bf16(pa0.x, pa0.y);
        *(uint2*)&AS[0][ab + 0] = make_uint2(h, cvt2_bf16(pa0.x - bf16lo_f(h), pa0.y - bf16hi_f(h)));
        h = cvt2_bf16(pa0.z, pa0.w);
        *(uint2*)&AS[0][ab + 2] = make_uint2(h, cvt2_bf16(pa0.z - bf16lo_f(h), pa0.w - bf16hi_f(h)));
        h = cvt2_bf16(pa1.x, pa1.y);
        *(uint2*)&AS[0][ab + 4] = make_uint2(h, cvt2_bf16(pa1.x - bf16lo_f(h), pa1.y - bf16hi_f(h)));
        h = cvt2_bf16(pa1.z, pa1.w);
        *(uint2*)&AS[0][ab + 6] = make_uint2(h, cvt2_bf16(pa1.z - bf16lo_f(h), pa1.w - bf16hi_f(h)));
        const int bb2 = l_rowB * PST + l_kpB * 2;
        h = cvt2_bf16(pb0.x, pb0.y);
        *(uint2*)&BS[0][bb2 + 0] = make_uint2(h, cvt2_bf16(pb0.x - bf16lo_f(h), pb0.y - bf16hi_f(h)));
        h = cvt2_bf16(pb0.z, pb0.w);
        *(uint2*)&BS[0][bb2 + 2] = make_uint2(h, cvt2_bf16(pb0.z - bf16lo_f(h), pb0.w - bf16hi_f(h)));
    }

    int cur = 0;
    for (int k0 = 0; k0 < DIM; k0 += 16) {
        __syncthreads();
        const bool more = (k0 + 16 < DIM);
        if (more) {
            pa0 = *(const float4*)(Aptr + k0 + 16);
            pa1 = *(const float4*)(Aptr + k0 + 20);
            pb0 = *(const float4*)(Bptr + k0 + 16);
        }
        #pragma unroll
        for (int i = 0; i < 2; i++) {
            const int r0 = (wm * 32 + i * 16 + gid) * PST + tig * 2;
            const int r1 = r0 + 8 * PST;
            const uint2 p00 = *(const uint2*)&AS[cur][r0];
            const uint2 p01 = *(const uint2*)&AS[cur][r0 + 8];
            const uint2 p10 = *(const uint2*)&AS[cur][r1];
            const uint2 p11 = *(const uint2*)&AS[cur][r1 + 8];
            #pragma unroll
            for (int j = 0; j < 4; j++) {
                const int cb = (wn * 32 + j * 8 + gid) * PST + tig * 2;
                const uint2 q0 = *(const uint2*)&BS[cur][cb];
                const uint2 q1 = *(const uint2*)&BS[cur][cb + 8];
                const int t = i * 4 + j;
                mma16(acc[t].x, acc[t].y, acc[t].z, acc[t].w,
                      p00.x, p10.x, p01.x, p11.x, q0.x, q1.x);
                mma16(acc[t].x, acc[t].y, acc[t].z, acc[t].w,
                      p00.x, p10.x, p01.x, p11.x, q0.y, q1.y);
                mma16(acc[t].x, acc[t].y, acc[t].z, acc[t].w,
                      p00.y, p10.y, p01.y, p11.y, q0.x, q1.x);
            }
        }
        if (more) {
            const int nxt = cur ^ 1;
            const int ab = l_row * PST + l_kp * 2;
            uint32_t h;
            h = cvt2_bf16(pa0.x, pa0.y);
            *(uint2*)&AS[nxt][ab + 0] = make_uint2(h, cvt2_bf16(pa0.x - bf16lo_f(h), pa0.y - bf16hi_f(h)));
            h = cvt2_bf16(pa0.z, pa0.w);
            *(uint2*)&AS[nxt][ab + 2] = make_uint2(h, cvt2_bf16(pa0.z - bf16lo_f(h), pa0.w - bf16hi_f(h)));
            h = cvt2_bf16(pa1.x, pa1.y);
            *(uint2*)&AS[nxt][ab + 4] = make_uint2(h, cvt2_bf16(pa1.x - bf16lo_f(h), pa1.y - bf16hi_f(h)));
            h = cvt2_bf16(pa1.z, pa1.w);
            *(uint2*)&AS[nxt][ab + 6] = make_uint2(h, cvt2_bf16(pa1.z - bf16lo_f(h), pa1.w - bf16hi_f(h)));
            const int bb2 = l_rowB * PST + l_kpB * 2;
            h = cvt2_bf16(pb0.x, pb0.y);
            *(uint2*)&BS[nxt][bb2 + 0] = make_uint2(h, cvt2_bf16(pb0.x - bf16lo_f(h), pb0.y - bf16hi_f(h)));
            h = cvt2_bf16(pb0.z, pb0.w);
            *(uint2*)&BS[nxt][bb2 + 2] = make_uint2(h, cvt2_bf16(pb0.z - bf16lo_f(h), pb0.w - bf16hi_f(h)));
        }
        cur ^= 1;
    }

    #pragma unroll
    for (int i = 0; i < 2; i++) {
        const int r0 = rowBase + wm * 32 + i * 16 + gid;
        #pragma unroll
        for (int j = 0; j < 4; j++) {
            const int t = i * 4 + j;
            const int c0 = colBase + wn * 32 + j * 8 + tig * 2;
            const float b0v = bias[c0], b1v = bias[c0 + 1];
            out[(size_t)r0 * DIM + c0]           = acc[t].x + b0v;
            out[(size_t)r0 * DIM + c0 + 1]       = acc[t].y + b1v;
            out[(size_t)(r0 + 8) * DIM + c0]     = acc[t].z + b0v;
            out[(size_t)(r0 + 8) * DIM + c0 + 1] = acc[t].w + b1v;
        }
    }
}

// ---------------------------------------------------------------------------
// Flash attention, tf32 mma (UNCHANGED from passing R11 kernel).
// ---------------------------------------------------------------------------
constexpr int BC = 64;
constexpr int AST = 68;
constexpr int ATTN_SMEM = (128 + 64 + 64 + 128) * AST * 4;   // 104448 B

__global__ __launch_bounds__(256)
void attn_kernel()
{
    extern __shared__ uint32_t smu[];
    uint32_t* QS = smu;                 // [128][AST]
    uint32_t* KS = QS + 128 * AST;      // [64][AST]
    uint32_t* VS = KS + 64 * AST;       // [64][AST]
    uint32_t* PS = VS + 64 * AST;       // [128][AST]

    const int bh = blockIdx.x;
    const int qt = blockIdx.y;
    const int tid = threadIdx.x;
    const int lane = tid & 31;
    const int gid = lane >> 2, tig = lane & 3;
    const int w = tid >> 5;
    const int rb = w * 16;

    const float* Qg = g_q + (size_t)bh * SEQ * DH + (size_t)qt * 128 * DH;
    const float* Kg = g_k + (size_t)bh * SEQ * DH;
    const float* Vg = g_v + (size_t)bh * SEQ * DH;

    for (int idx = tid; idx < 128 * DH / 4; idx += 256) {
        const int row = idx >> 4, c4 = (idx & 15) * 4;
        float4 v = ((const float4*)Qg)[idx];
        QS[row * AST + c4 + 0] = cvt_tf32(v.x * SCALE);
        QS[row * AST + c4 + 1] = cvt_tf32(v.y * SCALE);
        QS[row * AST + c4 + 2] = cvt_tf32(v.z * SCALE);
        QS[row * AST + c4 + 3] = cvt_tf32(v.w * SCALE);
    }

    float4 o[8];
    #pragma unroll
    for (int j = 0; j < 8; j++) o[j] = make_float4(0.f, 0.f, 0.f, 0.f);
    float m0 = -3.0e38f, m1 = -3.0e38f;
    float l0 = 0.f, l1 = 0.f;

    for (int kt = 0; kt < SEQ / BC; kt++) {
        __syncthreads();
        const float4* Kg4 = (const float4*)(Kg + (size_t)kt * BC * DH);
        const float4* Vg4 = (const float4*)(Vg + (size_t)kt * BC * DH);
        for (int idx = tid; idx < BC * DH / 4; idx += 256) {
            const int key = idx >> 4, c4 = (idx & 15) * 4;
            float4 kv = Kg4[idx], vv = Vg4[idx];
            KS[key * AST + c4 + 0] = cvt_tf32(kv.x);
            KS[key * AST + c4 + 1] = cvt_tf32(kv.y);
            KS[key * AST + c4 + 2] = cvt_tf32(kv.z);
            KS[key * AST + c4 + 3] = cvt_tf32(kv.w);
            VS[key * AST + c4 + 0] = cvt_tf32(vv.x);
            VS[key * AST + c4 + 1] = cvt_tf32(vv.y);
            VS[key * AST + c4 + 2] = cvt_tf32(vv.z);
            VS[key * AST + c4 + 3] = cvt_tf32(vv.w);
        }
        __syncthreads();

        float4 s[8];
        #pragma unroll
        for (int j = 0; j < 8; j++) s[j] = make_float4(0.f, 0.f, 0.f, 0.f);
        #pragma unroll
        for (int kk = 0; kk < DH; kk += 8) {
            const int i0 = (rb + gid) * AST + kk + tig;
            const int i1 = (rb + gid + 8) * AST + kk + tig;
            const uint32_t a0 = QS[i0], a1 = QS[i1];
            const uint32_t a2 = QS[i0 + 4], a3 = QS[i1 + 4];
            #pragma unroll
            for (int j = 0; j < 8; j++) {
                const int bi = (j * 8 + gid) * AST + kk + tig;
                mma8(s[j].x, s[j].y, s[j].z, s[j].w,
                     a0, a1, a2, a3, KS[bi], KS[bi + 4]);
            }
        }

        float mt0 = -3.0e38f, mt1 = -3.0e38f;
        #pragma unroll
        for (int j = 0; j < 8; j++) {
            mt0 = fmaxf(mt0, fmaxf(s[j].x, s[j].y));
            mt1 = fmaxf(mt1, fmaxf(s[j].z, s[j].w));
        }
        mt0 = fmaxf(mt0, __shfl_xor_sync(0xffffffffu, mt0, 1));
        mt0 = fmaxf(mt0, __shfl_xor_sync(0xffffffffu, mt0, 2));
        mt1 = fmaxf(mt1, __shfl_xor_sync(0xffffffffu, mt1, 1));
        mt1 = fmaxf(mt1, __shfl_xor_sync(0xffffffffu, mt1, 2));
        const float mn0 = fmaxf(m0, mt0), mn1 = fmaxf(m1, mt1);
        const float al0 = __expf(m0 - mn0), al1 = __expf(m1 - mn1);
        m0 = mn0; m1 = mn1;

        float rs0 = 0.f, rs1 = 0.f;
        const int p0base = (rb + gid) * AST + tig * 2;
        const int p1base = (rb + gid + 8) * AST + tig * 2;
        #pragma unroll
        for (int j = 0; j < 8; j++) {
            const float e0 = __expf(s[j].x - mn0);
            const float e1 = __expf(s[j].y - mn0);
            const float e2 = __expf(s[j].z - mn1);
            const float e3 = __expf(s[j].w - mn1);
            rs0 += e0 + e1; rs1 += e2 + e3;
            PS[p0base + j * 8 + 0] = cvt_tf32(e0);
            PS[p0base + j * 8 + 1] = cvt_tf32(e1);
            PS[p1base + j * 8 + 0] = cvt_tf32(e2);
            PS[p1base + j * 8 + 1] = cvt_tf32(e3);
        }
        rs0 += __shfl_xor_sync(0xffffffffu, rs0, 1);
        rs0 += __shfl_xor_sync(0xffffffffu, rs0, 2);
        rs1 += __shfl_xor_sync(0xffffffffu, rs1, 1);
        rs1 += __shfl_xor_sync(0xffffffffu, rs1, 2);
        l0 = l0 * al0 + rs0;
        l1 = l1 * al1 + rs1;

        #pragma unroll
        for (int j = 0; j < 8; j++) {
            o[j].x *= al0; o[j].y *= al0;
            o[j].z *= al1; o[j].w *= al1;
        }
        __syncwarp();

        #pragma unroll
        for (int kk = 0; kk < BC; kk += 8) {
            const int i0 = (rb + gid) * AST + kk + tig;
            const int i1 = (rb + gid + 8) * AST + kk + tig;
            const uint32_t a0 = PS[i0], a1 = PS[i1];
            const uint32_t a2 = PS[i0 + 4], a3 = PS[i1 + 4];
            #pragma unroll
            for (int j = 0; j < 8; j++) {
                mma8(o[j].x, o[j].y, o[j].z, o[j].w,
                     a0, a1, a2, a3,
                     VS[(kk + tig) * AST + j * 8 + gid],
                     VS[(kk + tig + 4) * AST + j * 8 + gid]);
            }
        }
    }

    const int bb = bh / HEADS;
    const int head = bh % HEADS;
    const float inv0 = 1.0f / l0, inv1 = 1.0f / l1;
    const int n0 = qt * 128 + rb + gid;
    const int n1 = n0 + 8;
    float* dst0 = g_att + (size_t)(bb * SEQ + n0) * DIM + head * DH;
    float* dst1 = g_att + (size_t)(bb * SEQ + n1) * DIM + head * DH;
    #pragma unroll
    for (int j = 0; j < 8; j++) {
        const int col = j * 8 + tig * 2;
        dst0[col + 0] = o[j].x * inv0;
        dst0[col + 1] = o[j].y * inv0;
        dst1[col + 0] = o[j].z * inv1;
        dst1[col + 1] = o[j].w * inv1;
    }
}

// ---------------------------------------------------------------------------
// Launch
// ---------------------------------------------------------------------------
extern "C" void kernel_launch(void* const* d_in, const int* in_sizes, int n_in,
                              void* d_out, int out_size)
{
    const float* x     = (const float*)d_in[0];
    const float* w_qkv = (const float*)d_in[1];
    const float* b_qkv = (const float*)d_in[2];
    const float* w_out = (const float*)d_in[3];
    const float* b_out = (const float*)d_in[4];
    float* out = (float*)d_out;

    cudaFuncSetAttribute(attn_kernel,
                         cudaFuncAttributeMaxDynamicSharedMemorySize, ATTN_SMEM);

    // 1) QKV projection (split-bf16 tensor cores, scatter to [b,h,n,d])
    dim3 g1(3 * DIM / 64, MROWS / 128);   // (36, 64)
    gemm_qkv_bf16<<<g1, 256>>>(x, w_qkv, b_qkv);

    // 2) Flash attention (tf32 tensor cores)
    dim3 g2(BATCH * HEADS, SEQ / 128);    // (48, 16)
    attn_kernel<<<g2, 256, ATTN_SMEM>>>();

    // 3) Output projection (split-bf16 tensor cores; A = g_att internally)
    dim3 g3(DIM / 64, MROWS / 128);       // (12, 64)
    gemm_out_bf16<<<g3, 256>>>(w_out, b_out, out);
}

// round 14
// speedup vs baseline: 1.1828x; 1.0772x over previous
#include <cuda_runtime.h>
#include <math.h>
#include <stdint.h>

// Problem constants
constexpr int BATCH = 4;
constexpr int SEQ   = 2048;
constexpr int DIM   = 768;
constexpr int HEADS = 12;
constexpr int DH    = 64;              // head dim
constexpr int MROWS = BATCH * SEQ;     // 8192
constexpr float SCALE = 0.03608439182435161f;  // 768^-0.5

// ---------------------------------------------------------------------------
// Scratch (allocation-free: __device__ globals)
// ---------------------------------------------------------------------------
__device__ __align__(16) float g_q[(size_t)BATCH * HEADS * SEQ * DH];
__device__ __align__(16) float g_k[(size_t)BATCH * HEADS * SEQ * DH];
__device__ __align__(16) float g_v[(size_t)BATCH * HEADS * SEQ * DH];
__device__ __align__(16) float g_att[(size_t)BATCH * SEQ * DIM];

// ---------------------------------------------------------------------------
// Conversion helpers
// ---------------------------------------------------------------------------
__device__ __forceinline__ uint32_t cvt_tf32(float f) {
    uint32_t r;
    asm("cvt.rna.tf32.f32 %0, %1;" : "=r"(r) : "f"(f));
    return r;
}

// pack two floats to bf16x2 word: f0 -> low half, f1 -> high half
__device__ __forceinline__ uint32_t cvt2_bf16(float f0, float f1) {
    uint32_t r;
    asm("cvt.rn.bf16x2.f32 %0, %2, %1;" : "=r"(r) : "f"(f0), "f"(f1));
    return r;
}
__device__ __forceinline__ float bf16lo_f(uint32_t w) { return __uint_as_float(w << 16); }
__device__ __forceinline__ float bf16hi_f(uint32_t w) { return __uint_as_float(w & 0xffff0000u); }

// tf32 m16n8k8 mma (attention)
__device__ __forceinline__ void mma8(float& c0, float& c1, float& c2, float& c3,
                                     uint32_t a0, uint32_t a1, uint32_t a2, uint32_t a3,
                                     uint32_t b0, uint32_t b1) {
    asm volatile(
        "mma.sync.aligned.m16n8k8.row.col.f32.tf32.tf32.f32 "
        "{%0,%1,%2,%3}, {%4,%5,%6,%7}, {%8,%9}, {%0,%1,%2,%3};\n"
        : "+f"(c0), "+f"(c1), "+f"(c2), "+f"(c3)
        : "r"(a0), "r"(a1), "r"(a2), "r"(a3), "r"(b0), "r"(b1));
}

// bf16 m16n8k16 mma (projections)
__device__ __forceinline__ void mma16(float& c0, float& c1, float& c2, float& c3,
                                      uint32_t a0, uint32_t a1, uint32_t a2, uint32_t a3,
                                      uint32_t b0, uint32_t b1) {
    asm volatile(
        "mma.sync.aligned.m16n8k16.row.col.f32.bf16.bf16.f32 "
        "{%0,%1,%2,%3}, {%4,%5,%6,%7}, {%8,%9}, {%0,%1,%2,%3};\n"
        : "+f"(c0), "+f"(c1), "+f"(c2), "+f"(c3)
        : "r"(a0), "r"(a1), "r"(a2), "r"(a3), "r"(b0), "r"(b1));
}

// scatter one QKV element into g_q/g_k/g_v ([b,h,n,d] layout)
__device__ __forceinline__ void scatter_qkv(float v, int row, int col) {
    const int bb = row >> 11, nn = row & 2047;
    const int which = col / DIM;
    const int rem = col - which * DIM;
    const int head = rem >> 6, dd = rem & 63;
    float* dst = (which == 0) ? g_q : (which == 1) ? g_k : g_v;
    dst[((size_t)((bb * HEADS + head) * SEQ + nn) << 6) + dd] = v;
}

// ---------------------------------------------------------------------------
// Split-bf16 (3-term) GEMM. Block 128x64, BK=16, 256 threads, 8 warps as
// 4M x 2N, warp tile 32x32. hi/lo interleaved per k-pair (LDS.64 fragments);
// double-buffered; B fragments hoisted out of the i loop (i-invariant).
// NON-TEMPLATED twin kernels (templated duals trip the 128MiB mem guard).
// ---------------------------------------------------------------------------
constexpr int PST = 24;   // words per row: 8 kpairs * 2 (hi,lo) + 8 pad

__global__ __launch_bounds__(256)
void gemm_qkv_bf16(const float* __restrict__ A, const float* __restrict__ W,
                   const float* __restrict__ bias)
{
    __shared__ __align__(16) uint32_t AS[2][128 * PST];
    __shared__ __align__(16) uint32_t BS[2][64 * PST];

    const int tid = threadIdx.x;
    const int lane = tid & 31;
    const int gid = lane >> 2, tig = lane & 3;
    const int w = tid >> 5;
    const int wm = w >> 1;
    const int wn = w & 1;
    const int rowBase = blockIdx.y * 128;
    const int colBase = blockIdx.x * 64;

    const int l_row  = tid >> 1;          // A loader row 0..127
    const int l_kp   = (tid & 1) * 4;     // A loader kpair base 0 or 4
    const int l_rowB = tid >> 2;          // B loader row 0..63
    const int l_kpB  = (tid & 3) * 2;     // B loader kpair base 0,2,4,6

    float4 acc[8];
    #pragma unroll
    for (int t = 0; t < 8; t++) acc[t] = make_float4(0.f, 0.f, 0.f, 0.f);

    const float* Aptr = A + (size_t)(rowBase + l_row) * DIM + l_kp * 2;
    const float* Bptr = W + (size_t)(colBase + l_rowB) * DIM + l_kpB * 2;

    float4 pa0 = *(const float4*)(Aptr);
    float4 pa1 = *(const float4*)(Aptr + 4);
    float4 pb0 = *(const float4*)(Bptr);

    {
        const int ab = l_row * PST + l_kp * 2;
        uint32_t h;
        h = cvt2_bf16(pa0.x, pa0.y);
        *(uint2*)&AS[0][ab + 0] = make_uint2(h, cvt2_bf16(pa0.x - bf16lo_f(h), pa0.y - bf16hi_f(h)));
        h = cvt2_bf16(pa0.z, pa0.w);
        *(uint2*)&AS[0][ab + 2] = make_uint2(h, cvt2_bf16(pa0.z - bf16lo_f(h), pa0.w - bf16hi_f(h)));
        h = cvt2_bf16(pa1.x, pa1.y);
        *(uint2*)&AS[0][ab + 4] = make_uint2(h, cvt2_bf16(pa1.x - bf16lo_f(h), pa1.y - bf16hi_f(h)));
        h = cvt2_bf16(pa1.z, pa1.w);
        *(uint2*)&AS[0][ab + 6] = make_uint2(h, cvt2_bf16(pa1.z - bf16lo_f(h), pa1.w - bf16hi_f(h)));
        const int bb2 = l_rowB * PST + l_kpB * 2;
        h = cvt2_bf16(pb0.x, pb0.y);
        *(uint2*)&BS[0][bb2 + 0] = make_uint2(h, cvt2_bf16(pb0.x - bf16lo_f(h), pb0.y - bf16hi_f(h)));
        h = cvt2_bf16(pb0.z, pb0.w);
        *(uint2*)&BS[0][bb2 + 2] = make_uint2(h, cvt2_bf16(pb0.z - bf16lo_f(h), pb0.w - bf16hi_f(h)));
    }

    int cur = 0;
    for (int k0 = 0; k0 < DIM; k0 += 16) {
        __syncthreads();
        const bool more = (k0 + 16 < DIM);
        if (more) {
            pa0 = *(const float4*)(Aptr + k0 + 16);
            pa1 = *(const float4*)(Aptr + k0 + 20);
            pb0 = *(const float4*)(Bptr + k0 + 16);
        }
        // hoisted B fragments (i-invariant)
        uint2 q0[4], q1[4];
        #pragma unroll
        for (int j = 0; j < 4; j++) {
            const int cb = (wn * 32 + j * 8 + gid) * PST + tig * 2;
            q0[j] = *(const uint2*)&BS[cur][cb];
            q1[j] = *(const uint2*)&BS[cur][cb + 8];
        }
        #pragma unroll
        for (int i = 0; i < 2; i++) {
            const int r0 = (wm * 32 + i * 16 + gid) * PST + tig * 2;
            const int r1 = r0 + 8 * PST;
            const uint2 p00 = *(const uint2*)&AS[cur][r0];       // kpair tig
            const uint2 p01 = *(const uint2*)&AS[cur][r0 + 8];   // kpair tig+4
            const uint2 p10 = *(const uint2*)&AS[cur][r1];
            const uint2 p11 = *(const uint2*)&AS[cur][r1 + 8];
            #pragma unroll
            for (int j = 0; j < 4; j++) {
                const int t = i * 4 + j;
                mma16(acc[t].x, acc[t].y, acc[t].z, acc[t].w,
                      p00.x, p10.x, p01.x, p11.x, q0[j].x, q1[j].x);   // hi*hi
                mma16(acc[t].x, acc[t].y, acc[t].z, acc[t].w,
                      p00.x, p10.x, p01.x, p11.x, q0[j].y, q1[j].y);   // hi*lo
                mma16(acc[t].x, acc[t].y, acc[t].z, acc[t].w,
                      p00.y, p10.y, p01.y, p11.y, q0[j].x, q1[j].x);   // lo*hi
            }
        }
        if (more) {
            const int nxt = cur ^ 1;
            const int ab = l_row * PST + l_kp * 2;
            uint32_t h;
            h = cvt2_bf16(pa0.x, pa0.y);
            *(uint2*)&AS[nxt][ab + 0] = make_uint2(h, cvt2_bf16(pa0.x - bf16lo_f(h), pa0.y - bf16hi_f(h)));
            h = cvt2_bf16(pa0.z, pa0.w);
            *(uint2*)&AS[nxt][ab + 2] = make_uint2(h, cvt2_bf16(pa0.z - bf16lo_f(h), pa0.w - bf16hi_f(h)));
            h = cvt2_bf16(pa1.x, pa1.y);
            *(uint2*)&AS[nxt][ab + 4] = make_uint2(h, cvt2_bf16(pa1.x - bf16lo_f(h), pa1.y - bf16hi_f(h)));
            h = cvt2_bf16(pa1.z, pa1.w);
            *(uint2*)&AS[nxt][ab + 6] = make_uint2(h, cvt2_bf16(pa1.z - bf16lo_f(h), pa1.w - bf16hi_f(h)));
            const int bb2 = l_rowB * PST + l_kpB * 2;
            h = cvt2_bf16(pb0.x, pb0.y);
            *(uint2*)&BS[nxt][bb2 + 0] = make_uint2(h, cvt2_bf16(pb0.x - bf16lo_f(h), pb0.y - bf16hi_f(h)));
            h = cvt2_bf16(pb0.z, pb0.w);
            *(uint2*)&BS[nxt][bb2 + 2] = make_uint2(h, cvt2_bf16(pb0.z - bf16lo_f(h), pb0.w - bf16hi_f(h)));
        }
        cur ^= 1;
    }

    #pragma unroll
    for (int i = 0; i < 2; i++) {
        const int r0 = rowBase + wm * 32 + i * 16 + gid;
        #pragma unroll
        for (int j = 0; j < 4; j++) {
            const int t = i * 4 + j;
            const int c0 = colBase + wn * 32 + j * 8 + tig * 2;
            const float b0v = bias[c0], b1v = bias[c0 + 1];
            scatter_qkv(acc[t].x + b0v, r0,     c0);
            scatter_qkv(acc[t].y + b1v, r0,     c0 + 1);
            scatter_qkv(acc[t].z + b0v, r0 + 8, c0);
            scatter_qkv(acc[t].w + b1v, r0 + 8, c0 + 1);
        }
    }
}

__global__ __launch_bounds__(256)
void gemm_out_bf16(const float* __restrict__ W, const float* __restrict__ bias,
                   float* __restrict__ out)
{
    __shared__ __align__(16) uint32_t AS[2][128 * PST];
    __shared__ __align__(16) uint32_t BS[2][64 * PST];

    const int tid = threadIdx.x;
    const int lane = tid & 31;
    const int gid = lane >> 2, tig = lane & 3;
    const int w = tid >> 5;
    const int wm = w >> 1;
    const int wn = w & 1;
    const int rowBase = blockIdx.y * 128;
    const int colBase = blockIdx.x * 64;

    const int l_row  = tid >> 1;
    const int l_kp   = (tid & 1) * 4;
    const int l_rowB = tid >> 2;
    const int l_kpB  = (tid & 3) * 2;

    float4 acc[8];
    #pragma unroll
    for (int t = 0; t < 8; t++) acc[t] = make_float4(0.f, 0.f, 0.f, 0.f);

    const float* Aptr = g_att + (size_t)(rowBase + l_row) * DIM + l_kp * 2;
    const float* Bptr = W + (size_t)(colBase + l_rowB) * DIM + l_kpB * 2;

    float4 pa0 = *(const float4*)(Aptr);
    float4 pa1 = *(const float4*)(Aptr + 4);
    float4 pb0 = *(const float4*)(Bptr);

    {
        const int ab = l_row * PST + l_kp * 2;
        uint32_t h;
        h = cvt2_bf16(pa0.x, pa0.y);
        *(uint2*)&AS[0][ab + 0] = make_uint2(h, cvt2_bf16(pa0.x - bf16lo_f(h), pa0.y - bf16hi_f(h)));
        h = cvt2_bf16(pa0.z, pa0.w);
        *(uint2*)&AS[0][ab + 2] = make_uint2(h, cvt2_bf16(pa0.z - bf16lo_f(h), pa0.w - bf16hi_f(h)));
        h = cvt2_bf16(pa1.x, pa1.y);
        *(uint2*)&AS[0][ab + 4] = make_uint2(h, cvt2_bf16(pa1.x - bf16lo_f(h), pa1.y - bf16hi_f(h)));
        h = cvt2_bf16(pa1.z, pa1.w);
        *(uint2*)&AS[0][ab + 6] = make_uint2(h, cvt2_bf16(pa1.z - bf16lo_f(h), pa1.w - bf16hi_f(h)));
        const int bb2 = l_rowB * PST + l_kpB * 2;
        h = cvt2_bf16(pb0.x, pb0.y);
        *(uint2*)&BS[0][bb2 + 0] = make_uint2(h, cvt2_bf16(pb0.x - bf16lo_f(h), pb0.y - bf16hi_f(h)));
        h = cvt2_bf16(pb0.z, pb0.w);
        *(uint2*)&BS[0][bb2 + 2] = make_uint2(h, cvt2_bf16(pb0.z - bf16lo_f(h), pb0.w - bf16hi_f(h)));
    }

    int cur = 0;
    for (int k0 = 0; k0 < DIM; k0 += 16) {
        __syncthreads();
        const bool more = (k0 + 16 < DIM);
        if (more) {
            pa0 = *(const float4*)(Aptr + k0 + 16);
            pa1 = *(const float4*)(Aptr + k0 + 20);
            pb0 = *(const float4*)(Bptr + k0 + 16);
        }
        uint2 q0[4], q1[4];
        #pragma unroll
        for (int j = 0; j < 4; j++) {
            const int cb = (wn * 32 + j * 8 + gid) * PST + tig * 2;
            q0[j] = *(const uint2*)&BS[cur][cb];
            q1[j] = *(const uint2*)&BS[cur][cb + 8];
        }
        #pragma unroll
        for (int i = 0; i < 2; i++) {
            const int r0 = (wm * 32 + i * 16 + gid) * PST + tig * 2;
            const int r1 = r0 + 8 * PST;
            const uint2 p00 = *(const uint2*)&AS[cur][r0];
            const uint2 p01 = *(const uint2*)&AS[cur][r0 + 8];
            const uint2 p10 = *(const uint2*)&AS[cur][r1];
            const uint2 p11 = *(const uint2*)&AS[cur][r1 + 8];
            #pragma unroll
            for (int j = 0; j < 4; j++) {
                const int t = i * 4 + j;
                mma16(acc[t].x, acc[t].y, acc[t].z, acc[t].w,
                      p00.x, p10.x, p01.x, p11.x, q0[j].x, q1[j].x);
                mma16(acc[t].x, acc[t].y, acc[t].z, acc[t].w,
                      p00.x, p10.x, p01.x, p11.x, q0[j].y, q1[j].y);
                mma16(acc[t].x, acc[t].y, acc[t].z, acc[t].w,
                      p00.y, p10.y, p01.y, p11.y, q0[j].x, q1[j].x);
            }
        }
        if (more) {
            const int nxt = cur ^ 1;
            const int ab = l_row * PST + l_kp * 2;
            uint32_t h;
            h = cvt2_bf16(pa0.x, pa0.y);
            *(uint2*)&AS[nxt][ab + 0] = make_uint2(h, cvt2_bf16(pa0.x - bf16lo_f(h), pa0.y - bf16hi_f(h)));
            h = cvt2_bf16(pa0.z, pa0.w);
            *(uint2*)&AS[nxt][ab + 2] = make_uint2(h, cvt2_bf16(pa0.z - bf16lo_f(h), pa0.w - bf16hi_f(h)));
            h = cvt2_bf16(pa1.x, pa1.y);
            *(uint2*)&AS[nxt][ab + 4] = make_uint2(h, cvt2_bf16(pa1.x - bf16lo_f(h), pa1.y - bf16hi_f(h)));
            h = cvt2_bf16(pa1.z, pa1.w);
            *(uint2*)&AS[nxt][ab + 6] = make_uint2(h, cvt2_bf16(pa1.z - bf16lo_f(h), pa1.w - bf16hi_f(h)));
            const int bb2 = l_rowB * PST + l_kpB * 2;
            h = cvt2_bf16(pb0.x, pb0.y);
            *(uint2*)&BS[nxt][bb2 + 0] = make_uint2(h, cvt2_bf16(pb0.x - bf16lo_f(h), pb0.y - bf16hi_f(h)));
            h = cvt2_bf16(pb0.z, pb0.w);
            *(uint2*)&BS[nxt][bb2 + 2] = make_uint2(h, cvt2_bf16(pb0.z - bf16lo_f(h), pb0.w - bf16hi_f(h)));
        }
        cur ^= 1;
    }

    #pragma unroll
    for (int i = 0; i < 2; i++) {
        const int r0 = rowBase + wm * 32 + i * 16 + gid;
        #pragma unroll
        for (int j = 0; j < 4; j++) {
            const int t = i * 4 + j;
            const int c0 = colBase + wn * 32 + j * 8 + tig * 2;
            const float b0v = bias[c0], b1v = bias[c0 + 1];
            out[(size_t)r0 * DIM + c0]           = acc[t].x + b0v;
            out[(size_t)r0 * DIM + c0 + 1]       = acc[t].y + b1v;
            out[(size_t)(r0 + 8) * DIM + c0]     = acc[t].z + b0v;
            out[(size_t)(r0 + 8) * DIM + c0 + 1] = acc[t].w + b1v;
        }
    }
}

// ---------------------------------------------------------------------------
// Flash attention, tf32 mma with PAIR-PERMUTED k-columns:
// within each 8-col k-group, column c sits at word (c&3)*2 + (c>>2), so the
// mma fragment pair (k, k+4) is adjacent -> single LDS.64. AST=72 makes the
// 64-bit lane addresses conflict-free ((row*36+tig) mod 16 distinct).
// QS/KS/PS use the permuted layout; VS stays linear (row-paired reads).
// ---------------------------------------------------------------------------
constexpr int BC = 64;
constexpr int AST = 72;
constexpr int ATTN_SMEM = (128 + 64 + 64 + 128) * AST * 4;   // 110592 B

__global__ __launch_bounds__(256)
void attn_kernel()
{
    extern __shared__ uint32_t smu[];
    uint32_t* QS = smu;                 // [128][AST] permuted
    uint32_t* KS = QS + 128 * AST;      // [64][AST]  permuted
    uint32_t* VS = KS + 64 * AST;       // [64][AST]  linear
    uint32_t* PS = VS + 64 * AST;       // [128][AST] permuted

    const int bh = blockIdx.x;
    const int qt = blockIdx.y;
    const int tid = threadIdx.x;
    const int lane = tid & 31;
    const int gid = lane >> 2, tig = lane & 3;
    const int w = tid >> 5;
    const int rb = w * 16;

    const float* Qg = g_q + (size_t)bh * SEQ * DH + (size_t)qt * 128 * DH;
    const float* Kg = g_k + (size_t)bh * SEQ * DH;
    const float* Vg = g_v + (size_t)bh * SEQ * DH;

    // Load + scale + tf32 + permute Q tile. c4 = 0 or 4 mod 8 -> the 4
    // consecutive columns land at positions (c4&4 ? 1 : 0) + 2e in the group.
    for (int idx = tid; idx < 128 * DH / 4; idx += 256) {
        const int row = idx >> 4, c4 = (idx & 15) * 4;
        const int base = row * AST + (c4 & ~7) + ((c4 & 4) ? 1 : 0);
        float4 v = ((const float4*)Qg)[idx];
        QS[base + 0] = cvt_tf32(v.x * SCALE);
        QS[base + 2] = cvt_tf32(v.y * SCALE);
        QS[base + 4] = cvt_tf32(v.z * SCALE);
        QS[base + 6] = cvt_tf32(v.w * SCALE);
    }

    float4 o[8];
    #pragma unroll
    for (int j = 0; j < 8; j++) o[j] = make_float4(0.f, 0.f, 0.f, 0.f);
    float m0 = -3.0e38f, m1 = -3.0e38f;
    float l0 = 0.f, l1 = 0.f;

    // P store positions (inverse permutation of columns tig*2, tig*2+1)
    const int pc0 = ((tig * 2) & 3) * 2 + (tig >> 1);
    const int pc1 = ((tig * 2 + 1) & 3) * 2 + (tig >> 1);

    for (int kt = 0; kt < SEQ / BC; kt++) {
        __syncthreads();
        const float4* Kg4 = (const float4*)(Kg + (size_t)kt * BC * DH);
        const float4* Vg4 = (const float4*)(Vg + (size_t)kt * BC * DH);
        for (int idx = tid; idx < BC * DH / 4; idx += 256) {
            const int key = idx >> 4, c4 = (idx & 15) * 4;
            float4 kv = Kg4[idx], vv = Vg4[idx];
            const int kb = key * AST + (c4 & ~7) + ((c4 & 4) ? 1 : 0);
            KS[kb + 0] = cvt_tf32(kv.x);
            KS[kb + 2] = cvt_tf32(kv.y);
            KS[kb + 4] = cvt_tf32(kv.z);
            KS[kb + 6] = cvt_tf32(kv.w);
            const int vb = key * AST + c4;          // linear
            VS[vb + 0] = cvt_tf32(vv.x);
            VS[vb + 1] = cvt_tf32(vv.y);
            VS[vb + 2] = cvt_tf32(vv.z);
            VS[vb + 3] = cvt_tf32(vv.w);
        }
        __syncthreads();

        // S = Q * K^T : all fragments via LDS.64
        float4 s[8];
        #pragma unroll
        for (int j = 0; j < 8; j++) s[j] = make_float4(0.f, 0.f, 0.f, 0.f);
        #pragma unroll
        for (int kk = 0; kk < DH; kk += 8) {
            const uint2 pA0 = *(const uint2*)&QS[(rb + gid) * AST + kk + tig * 2];
            const uint2 pA1 = *(const uint2*)&QS[(rb + gid + 8) * AST + kk + tig * 2];
            #pragma unroll
            for (int j = 0; j < 8; j++) {
                const uint2 pB = *(const uint2*)&KS[(j * 8 + gid) * AST + kk + tig * 2];
                mma8(s[j].x, s[j].y, s[j].z, s[j].w,
                     pA0.x, pA1.x, pA0.y, pA1.y, pB.x, pB.y);
            }
        }

        float mt0 = -3.0e38f, mt1 = -3.0e38f;
        #pragma unroll
        for (int j = 0; j < 8; j++) {
            mt0 = fmaxf(mt0, fmaxf(s[j].x, s[j].y));
            mt1 = fmaxf(mt1, fmaxf(s[j].z, s[j].w));
        }
        mt0 = fmaxf(mt0, __shfl_xor_sync(0xffffffffu, mt0, 1));
        mt0 = fmaxf(mt0, __shfl_xor_sync(0xffffffffu, mt0, 2));
        mt1 = fmaxf(mt1, __shfl_xor_sync(0xffffffffu, mt1, 1));
        mt1 = fmaxf(mt1, __shfl_xor_sync(0xffffffffu, mt1, 2));
        const float mn0 = fmaxf(m0, mt0), mn1 = fmaxf(m1, mt1);
        const float al0 = __expf(m0 - mn0), al1 = __expf(m1 - mn1);
        m0 = mn0; m1 = mn1;

        float rs0 = 0.f, rs1 = 0.f;
        const int p0base = (rb + gid) * AST;
        const int p1base = (rb + gid + 8) * AST;
        #pragma unroll
        for (int j = 0; j < 8; j++) {
            const float e0 = __expf(s[j].x - mn0);
            const float e1 = __expf(s[j].y - mn0);
            const float e2 = __expf(s[j].z - mn1);
            const float e3 = __expf(s[j].w - mn1);
            rs0 += e0 + e1; rs1 += e2 + e3;
            PS[p0base + j * 8 + pc0] = cvt_tf32(e0);
            PS[p0base + j * 8 + pc1] = cvt_tf32(e1);
            PS[p1base + j * 8 + pc0] = cvt_tf32(e2);
            PS[p1base + j * 8 + pc1] = cvt_tf32(e3);
        }
        rs0 += __shfl_xor_sync(0xffffffffu, rs0, 1);
        rs0 += __shfl_xor_sync(0xffffffffu, rs0, 2);
        rs1 += __shfl_xor_sync(0xffffffffu, rs1, 1);
        rs1 += __shfl_xor_sync(0xffffffffu, rs1, 2);
        l0 = l0 * al0 + rs0;
        l1 = l1 * al1 + rs1;

        #pragma unroll
        for (int j = 0; j < 8; j++) {
            o[j].x *= al0; o[j].y *= al0;
            o[j].z *= al1; o[j].w *= al1;
        }
        __syncwarp();

        // O += P * V : A fragments LDS.64 (permuted PS); V scalar (linear)
        #pragma unroll
        for (int kk = 0; kk < BC; kk += 8) {
            const uint2 pA0 = *(const uint2*)&PS[(rb + gid) * AST + kk + tig * 2];
            const uint2 pA1 = *(const uint2*)&PS[(rb + gid + 8) * AST + kk + tig * 2];
            #pragma unroll
            for (int j = 0; j < 8; j++) {
                mma8(o[j].x, o[j].y, o[j].z, o[j].w,
                     pA0.x, pA1.x, pA0.y, pA1.y,
                     VS[(kk + tig) * AST + j * 8 + gid],
                     VS[(kk + tig + 4) * AST + j * 8 + gid]);
            }
        }
    }

    const int bb = bh / HEADS;
    const int head = bh % HEADS;
    const float inv0 = 1.0f / l0, inv1 = 1.0f / l1;
    const int n0 = qt * 128 + rb + gid;
    const int n1 = n0 + 8;
    float* dst0 = g_att + (size_t)(bb * SEQ + n0) * DIM + head * DH;
    float* dst1 = g_att + (size_t)(bb * SEQ + n1) * DIM + head * DH;
    #pragma unroll
    for (int j = 0; j < 8; j++) {
        const int col = j * 8 + tig * 2;
        dst0[col + 0] = o[j].x * inv0;
        dst0[col + 1] = o[j].y * inv0;
        dst1[col + 0] = o[j].z * inv1;
        dst1[col + 1] = o[j].w * inv1;
    }
}

// ---------------------------------------------------------------------------
// Launch
// ---------------------------------------------------------------------------
extern "C" void kernel_launch(void* const* d_in, const int* in_sizes, int n_in,
                              void* d_out, int out_size)
{
    const float* x     = (const float*)d_in[0];
    const float* w_qkv = (const float*)d_in[1];
    const float* b_qkv = (const float*)d_in[2];
    const float* w_out = (const float*)d_in[3];
    const float* b_out = (const float*)d_in[4];
    float* out = (float*)d_out;

    cudaFuncSetAttribute(attn_kernel,
                         cudaFuncAttributeMaxDynamicSharedMemorySize, ATTN_SMEM);

    // 1) QKV projection (split-bf16 tensor cores, scatter to [b,h,n,d])
    dim3 g1(3 * DIM / 64, MROWS / 128);   // (36, 64)
    gemm_qkv_bf16<<<g1, 256>>>(x, w_qkv, b_qkv);

    // 2) Flash attention (tf32 tensor cores)
    dim3 g2(BATCH * HEADS, SEQ / 128);    // (48, 16)
    attn_kernel<<<g2, 256, ATTN_SMEM>>>();

    // 3) Output projection (split-bf16 tensor cores; A = g_att internally)
    dim3 g3(DIM / 64, MROWS / 128);       // (12, 64)
    gemm_out_bf16<<<g3, 256>>>(w_out, b_out, out);
}